// round 5
// baseline (speedup 1.0000x reference)
#include <cuda_runtime.h>
#include <cuda_bf16.h>
#include <math.h>
#include <stdint.h>

#define NB 64
#define NC 64
#define NH 56
#define NW 56
#define HW 3136
#define CHW 200704
#define OUT_MAIN (NB*CHW)

__device__ float g_y1[NB*2*CHW];
__device__ int   g_eidx[NB*2];
__device__ float g_ewt[NB*2];
__device__ float g_pooled[NB*NC];

// ---- SMEM layout (bytes) ----
#define SM_W    0
#define WTILE   16384                 // per tap: Wh 8KB (64x128B) + Wl 8KB
#define SM_RING (9*WTILE)             // 147456
#define SLOT_H  8448                  // 66 rows x 128B
#define SLOT    16896                 // hi + lo
#define SM_BUF  (SM_RING + 4*SLOT)    // 215040
#define SM_TOTAL (SM_BUF + 16384)     // 231424 <= 232448

__device__ __forceinline__ uint32_t smem_u32(const void* p){
    uint32_t a; asm("{ .reg .u64 t; cvta.to.shared.u64 t, %1; cvt.u32.u64 %0, t; }":"=r"(a):"l"(p)); return a;
}

#define LDSM4(d0,d1,d2,d3,a) \
    asm volatile("ldmatrix.sync.aligned.m8n8.x4.shared.b16 {%0,%1,%2,%3},[%4];" \
        : "=r"(d0),"=r"(d1),"=r"(d2),"=r"(d3) : "r"(a))

#define MMA16816(C,a0,a1,a2,a3,b0,b1) \
    asm volatile("mma.sync.aligned.m16n8k16.row.col.f32.bf16.bf16.f32 " \
        "{%0,%1,%2,%3},{%4,%5,%6,%7},{%8,%9},{%0,%1,%2,%3};" \
        : "+f"((C)[0]),"+f"((C)[1]),"+f"((C)[2]),"+f"((C)[3]) \
        : "r"(a0),"r"(a1),"r"(a2),"r"(a3),"r"(b0),"r"(b1))

// ---------------------------------------------------------------------------
// Gate: pooling (grid 64x8) + finalize (1x64)
// ---------------------------------------------------------------------------
__global__ void pool_kernel(const float* __restrict__ x){
    int b = blockIdx.x, gg = blockIdx.y;
    int w = threadIdx.x>>5, l = threadIdx.x&31;
    int c = gg*8 + w;
    const float4* p = (const float4*)(x + ((size_t)b*NC + c)*HW);
    float s = 0.f;
    for (int i=l; i<HW/4; i+=32){ float4 v = p[i]; s += (v.x+v.y)+(v.z+v.w); }
    #pragma unroll
    for (int o=16;o>0;o>>=1) s += __shfl_xor_sync(0xffffffffu, s, o);
    if (l==0) g_pooled[b*NC+c] = s * (1.0f/(float)HW);
}

__global__ void gate_fin(const float* __restrict__ gw, const float* __restrict__ gb,
                         float* __restrict__ dw){
    int b = threadIdx.x;
    if (b >= NB) return;
    float lg[8];
    #pragma unroll
    for (int e=0;e<8;e++){
        float s = gb[e];
        for (int c=0;c<NC;c++) s += g_pooled[b*NC+c]*gw[e*NC+c];
        lg[e] = s;
    }
    int i0=0; float v0=lg[0];
    #pragma unroll
    for (int e=1;e<8;e++) if (lg[e]>v0){ v0=lg[e]; i0=e; }
    int i1=-1; float v1=-1e30f;
    #pragma unroll
    for (int e=0;e<8;e++){ if (e==i0) continue; if (lg[e]>v1){ v1=lg[e]; i1=e; } }
    float w0 = 1.0f/(1.0f+expf(v1-v0));
    float w1 = 1.0f-w0;
    g_eidx[b*2+0]=i0; g_eidx[b*2+1]=i1;
    g_ewt [b*2+0]=w0; g_ewt [b*2+1]=w1;
    if (dw){ dw[b*8+i0]=w0; dw[b*8+i1]=w1; }
}

// ---------------------------------------------------------------------------
// Stage input row yy into ring slot (yy&3): rows c = x+1 (1..56), cols = cin.
// Rows 0, 57..65 stay zero (initialized once). bf16 hi + lo split. 256 thr.
// ---------------------------------------------------------------------------
__device__ __forceinline__ void stage_row(char* smem, const float* __restrict__ in, int yy){
    int ci = threadIdx.x >> 2, q = threadIdx.x & 3;
    uint32_t base = SM_RING + (uint32_t)(yy&3)*SLOT;
    const float* src = in + (size_t)ci*HW + yy*NW + q*14;
    uint32_t cb2 = (uint32_t)(ci*2);
    #pragma unroll 7
    for (int j=0;j<14;j++){
        int x = q*14 + j;
        float v = src[j];
        __nv_bfloat16 h = __float2bfloat16(v);
        __nv_bfloat16 l = __float2bfloat16(v - __bfloat162float(h));
        uint32_t c = (uint32_t)(x+1);
        uint32_t off = base + c*128 + (cb2 ^ ((c&7)<<4));
        *(__nv_bfloat16*)(smem+off) = h;
        *(__nv_bfloat16*)(smem+off+SLOT_H) = l;
    }
}

// ---------------------------------------------------------------------------
// Persistent conv per (b,slot), HMMA, 8 warps: 2x2 (M32,N32) tiles x 2 K-halves.
// MODE1: g_y1 = relu(bn1(conv(x)))
// MODE2: out += wt * relu(bn2(conv(g_y1)) + x)
// ---------------------------------------------------------------------------
template<int MODE>
__global__ void __launch_bounds__(256,1) conv_hmma(
    const float* __restrict__ x, const float* __restrict__ w_all,
    const float* __restrict__ bn_s, const float* __restrict__ bn_b,
    float* __restrict__ out)
{
    extern __shared__ char smem[];
    const int tid = threadIdx.x, wid = tid>>5, lane = tid&31;
    const int pr  = wid & 3;            // tile position
    const int half= wid >> 2;           // K half
    const int wm = pr>>1, wn = pr&1;    // M tile wm*32, N tile wn*32
    const int bs = blockIdx.x, b = bs>>1;
    const int e = g_eidx[bs];
    const float wt = g_ewt[bs];
    const float* in   = (MODE==1) ? x + (size_t)b*CHW : g_y1 + (size_t)bs*CHW;
    const float* xres = x + (size_t)b*CHW;
    float* dst = (MODE==1) ? g_y1 + (size_t)bs*CHW : out + (size_t)b*CHW;
    const uint32_t sbase = smem_u32(smem);
    float* buf = (float*)(smem + SM_BUF);

    // zero ring (rows never re-written stay zero: halo + n>=56 pad)
    for (int i=tid; i<(4*SLOT)/4; i+=256) ((uint32_t*)(smem+SM_RING))[i] = 0;

    // stage weights once: tap g tile = [Wh rows co | +8192 Wl], swizzled
    const float* wb = w_all + (size_t)e*NC*NC*9;
    for (int p=tid; p<4096; p+=256){
        int co = p>>6, ci = p&63;
        const float* wp = wb + (size_t)p*9;
        uint32_t sx = (uint32_t)((co&7)<<4);
        uint32_t ro = (uint32_t)co*128;
        uint32_t cb = (uint32_t)(ci*2);
        #pragma unroll
        for (int g9=0; g9<9; g9++){
            float v = wp[g9];
            __nv_bfloat16 h = __float2bfloat16(v);
            __nv_bfloat16 l = __float2bfloat16(v - __bfloat162float(h));
            uint32_t off = SM_W + (uint32_t)g9*WTILE + ro + (cb ^ sx);
            *(__nv_bfloat16*)(smem+off) = h;
            *(__nv_bfloat16*)(smem+off+8192) = l;
        }
    }
    stage_row(smem, in, 0);
    stage_row(smem, in, 1);

    // per-thread bn params (epilogue warps only use them)
    const int g = lane>>2;
    float scv[2][2], biv[2][2];
    #pragma unroll
    for (int mt=0; mt<2; mt++){
        int co0 = wm*32 + mt*16 + g;
        scv[mt][0] = bn_s[e*NC+co0];   biv[mt][0] = bn_b[e*NC+co0];
        scv[mt][1] = bn_s[e*NC+co0+8]; biv[mt][1] = bn_b[e*NC+co0+8];
    }
    __syncthreads();

    // per-lane ldmatrix constants
    const int sub = lane>>3, r = lane&7;
    uint32_t rAoff[2], sxA[2];
    #pragma unroll
    for (int mt=0; mt<2; mt++){
        uint32_t rowA = (uint32_t)(wm*32 + mt*16 + (sub&1)*8 + r);
        rAoff[mt] = rowA*128;
        sxA[mt]   = (rowA&7)<<4;
    }
    const uint32_t kbA0 = (uint32_t)((sub>>1)*16);
    const uint32_t rb0  = (uint32_t)(wn*32 + (sub>>1)*8 + r);
    const uint32_t kbB0 = (uint32_t)((sub&1)*16);

    for (int y=0; y<NH; y++){
        if (y+2 < NH) stage_row(smem, in, y+2);

        float C[2][4][4];
        #pragma unroll
        for (int mt=0;mt<2;mt++)
            #pragma unroll
            for (int j=0;j<4;j++)
                #pragma unroll
                for (int q=0;q<4;q++) C[mt][j][q]=0.f;

        for (int ky=0; ky<3; ky++){
            int yy = y+ky-1;
            if (yy<0 || yy>=NH) continue;
            uint32_t slotB = sbase + SM_RING + (uint32_t)(yy&3)*SLOT;
            #pragma unroll
            for (int kx=0; kx<3; kx++){
                uint32_t aT = sbase + SM_W + (uint32_t)(3*ky+kx)*WTILE;
                #pragma unroll
                for (int kh=0; kh<2; kh++){
                    int ks = half*2 + kh;
                    uint32_t kA = kbA0 + (uint32_t)ks*32;
                    uint32_t kB = kbB0 + (uint32_t)ks*32;
                    uint32_t ah[2][4], al[2][4], bh[2][4], bl[2][4];
                    #pragma unroll
                    for (int mt=0; mt<2; mt++){
                        uint32_t a0 = aT + rAoff[mt] + (kA ^ sxA[mt]);
                        LDSM4(ah[mt][0],ah[mt][1],ah[mt][2],ah[mt][3], a0);
                        LDSM4(al[mt][0],al[mt][1],al[mt][2],al[mt][3], a0 + 8192);
                    }
                    #pragma unroll
                    for (int nt=0; nt<2; nt++){
                        uint32_t rb = rb0 + (uint32_t)(kx + nt*16);
                        uint32_t b0 = slotB + rb*128 + (kB ^ ((rb&7)<<4));
                        LDSM4(bh[nt][0],bh[nt][1],bh[nt][2],bh[nt][3], b0);
                        LDSM4(bl[nt][0],bl[nt][1],bl[nt][2],bl[nt][3], b0 + SLOT_H);
                    }
                    #pragma unroll
                    for (int mt=0;mt<2;mt++){
                        #pragma unroll
                        for (int nt=0;nt<2;nt++){
                            float* Cl = C[mt][nt*2];
                            float* Ch = C[mt][nt*2+1];
                            MMA16816(Cl, ah[mt][0],ah[mt][1],ah[mt][2],ah[mt][3], bh[nt][0],bh[nt][1]);
                            MMA16816(Cl, ah[mt][0],ah[mt][1],ah[mt][2],ah[mt][3], bl[nt][0],bl[nt][1]);
                            MMA16816(Cl, al[mt][0],al[mt][1],al[mt][2],al[mt][3], bh[nt][0],bh[nt][1]);
                            MMA16816(Ch, ah[mt][0],ah[mt][1],ah[mt][2],ah[mt][3], bh[nt][2],bh[nt][3]);
                            MMA16816(Ch, ah[mt][0],ah[mt][1],ah[mt][2],ah[mt][3], bl[nt][2],bl[nt][3]);
                            MMA16816(Ch, al[mt][0],al[mt][1],al[mt][2],al[mt][3], bh[nt][2],bh[nt][3]);
                        }
                    }
                }
            }
        }

        // K-half reduction: upper warps dump partial C, lower warps add + epilogue
        __syncthreads();
        if (half==1){
            float4* p = (float4*)(buf + (pr*32+lane)*32);
            #pragma unroll
            for (int mt=0;mt<2;mt++)
                #pragma unroll
                for (int j=0;j<4;j++)
                    p[mt*4+j] = make_float4(C[mt][j][0],C[mt][j][1],C[mt][j][2],C[mt][j][3]);
        }
        __syncthreads();
        if (half==0){
            const float4* p = (const float4*)(buf + (pr*32+lane)*32);
            #pragma unroll
            for (int mt=0;mt<2;mt++)
                #pragma unroll
                for (int j=0;j<4;j++){
                    float4 v = p[mt*4+j];
                    C[mt][j][0]+=v.x; C[mt][j][1]+=v.y; C[mt][j][2]+=v.z; C[mt][j][3]+=v.w;
                }

            int xq = 2*(lane&3);
            #pragma unroll
            for (int mt=0;mt<2;mt++){
                int co0 = wm*32 + mt*16 + g, co1 = co0+8;
                #pragma unroll
                for (int j=0;j<4;j++){
                    int xx = wn*32 + j*8 + xq;
                    if (xx >= NW) continue;
                    float v0 = C[mt][j][0]*scv[mt][0] + biv[mt][0];
                    float v1 = C[mt][j][1]*scv[mt][0] + biv[mt][0];
                    float v2 = C[mt][j][2]*scv[mt][1] + biv[mt][1];
                    float v3 = C[mt][j][3]*scv[mt][1] + biv[mt][1];
                    int i0 = co0*HW + y*NW + xx;
                    int i1 = co1*HW + y*NW + xx;
                    if (MODE==1){
                        *(float2*)(dst+i0) = make_float2(fmaxf(v0,0.f), fmaxf(v1,0.f));
                        *(float2*)(dst+i1) = make_float2(fmaxf(v2,0.f), fmaxf(v3,0.f));
                    } else {
                        float2 r0 = *(const float2*)(xres+i0);
                        float2 r1 = *(const float2*)(xres+i1);
                        atomicAdd(dst+i0,   wt*fmaxf(v0+r0.x,0.f));
                        atomicAdd(dst+i0+1, wt*fmaxf(v1+r0.y,0.f));
                        atomicAdd(dst+i1,   wt*fmaxf(v2+r1.x,0.f));
                        atomicAdd(dst+i1+1, wt*fmaxf(v3+r1.y,0.f));
                    }
                }
            }
        }
        __syncthreads();
    }
}

// ---------------------------------------------------------------------------
extern "C" void kernel_launch(void* const* d_in, const int* in_sizes, int n_in,
                              void* d_out, int out_size)
{
    const float* x       = (const float*)d_in[0];
    const float* gate_w  = (const float*)d_in[1];
    const float* gate_b  = (const float*)d_in[2];
    const float* conv1_w = (const float*)d_in[3];
    const float* bn1_s   = (const float*)d_in[4];
    const float* bn1_b   = (const float*)d_in[5];
    const float* conv2_w = (const float*)d_in[6];
    const float* bn2_s   = (const float*)d_in[7];
    const float* bn2_b   = (const float*)d_in[8];
    float* out = (float*)d_out;

    cudaMemsetAsync(d_out, 0, (size_t)out_size*sizeof(float), 0);
    pool_kernel<<<dim3(NB,8), 256>>>(x);
    float* dw = (out_size >= OUT_MAIN + NB*8) ? (out + OUT_MAIN) : nullptr;
    gate_fin<<<1, 64>>>(gate_w, gate_b, dw);

    cudaFuncSetAttribute(conv_hmma<1>, cudaFuncAttributeMaxDynamicSharedMemorySize, SM_TOTAL);
    cudaFuncSetAttribute(conv_hmma<2>, cudaFuncAttributeMaxDynamicSharedMemorySize, SM_TOTAL);
    conv_hmma<1><<<128, 256, SM_TOTAL>>>(x, conv1_w, bn1_s, bn1_b, nullptr);
    conv_hmma<2><<<128, 256, SM_TOTAL>>>(x, conv2_w, bn2_s, bn2_b, out);
}

// round 6
// speedup vs baseline: 1.4541x; 1.4541x over previous
#include <cuda_runtime.h>
#include <cuda_fp16.h>
#include <math.h>
#include <stdint.h>

#define NB 64
#define NC 64
#define NH 56
#define NW 56
#define HW 3136
#define CHW 200704
#define OUT_MAIN (NB*CHW)

__device__ float g_y1[NB*2*CHW];
__device__ int   g_eidx[NB*2];
__device__ float g_ewt[NB*2];
__device__ float g_pooled[NB*NC];

// ---- SMEM layout (bytes) ----
#define SM_W    0
#define WTILE   16384                 // per tap: Wh 8KB (64x128B) + Wl 8KB
#define SM_RING (9*WTILE)             // 147456
#define SLOT    8448                  // 66 rows x 128B (fp16 hi only)
#define SM_TOTAL (SM_RING + 6*SLOT)   // 198144 <= 232448

__device__ __forceinline__ uint32_t smem_u32(const void* p){
    uint32_t a; asm("{ .reg .u64 t; cvta.to.shared.u64 t, %1; cvt.u32.u64 %0, t; }":"=r"(a):"l"(p)); return a;
}

#define LDSM4(d0,d1,d2,d3,a) \
    asm volatile("ldmatrix.sync.aligned.m8n8.x4.shared.b16 {%0,%1,%2,%3},[%4];" \
        : "=r"(d0),"=r"(d1),"=r"(d2),"=r"(d3) : "r"(a))

#define MMA16816(C,a0,a1,a2,a3,b0,b1) \
    asm volatile("mma.sync.aligned.m16n8k16.row.col.f32.f16.f16.f32 " \
        "{%0,%1,%2,%3},{%4,%5,%6,%7},{%8,%9},{%0,%1,%2,%3};" \
        : "+f"((C)[0]),"+f"((C)[1]),"+f"((C)[2]),"+f"((C)[3]) \
        : "r"(a0),"r"(a1),"r"(a2),"r"(a3),"r"(b0),"r"(b1))

// ---------------------------------------------------------------------------
// Gate: pooling (grid 64x8) + finalize (1x64)
// ---------------------------------------------------------------------------
__global__ void pool_kernel(const float* __restrict__ x){
    int b = blockIdx.x, gg = blockIdx.y;
    int w = threadIdx.x>>5, l = threadIdx.x&31;
    int c = gg*8 + w;
    const float4* p = (const float4*)(x + ((size_t)b*NC + c)*HW);
    float s = 0.f;
    for (int i=l; i<HW/4; i+=32){ float4 v = p[i]; s += (v.x+v.y)+(v.z+v.w); }
    #pragma unroll
    for (int o=16;o>0;o>>=1) s += __shfl_xor_sync(0xffffffffu, s, o);
    if (l==0) g_pooled[b*NC+c] = s * (1.0f/(float)HW);
}

__global__ void gate_fin(const float* __restrict__ gw, const float* __restrict__ gb,
                         float* __restrict__ dw){
    int b = threadIdx.x;
    if (b >= NB) return;
    float lg[8];
    #pragma unroll
    for (int e=0;e<8;e++){
        float s = gb[e];
        for (int c=0;c<NC;c++) s += g_pooled[b*NC+c]*gw[e*NC+c];
        lg[e] = s;
    }
    int i0=0; float v0=lg[0];
    #pragma unroll
    for (int e=1;e<8;e++) if (lg[e]>v0){ v0=lg[e]; i0=e; }
    int i1=-1; float v1=-1e30f;
    #pragma unroll
    for (int e=0;e<8;e++){ if (e==i0) continue; if (lg[e]>v1){ v1=lg[e]; i1=e; } }
    float w0 = 1.0f/(1.0f+expf(v1-v0));
    float w1 = 1.0f-w0;
    g_eidx[b*2+0]=i0; g_eidx[b*2+1]=i1;
    g_ewt [b*2+0]=w0; g_ewt [b*2+1]=w1;
    if (dw){ dw[b*8+i0]=w0; dw[b*8+i1]=w1; }
}

// ---------------------------------------------------------------------------
// Stage input row yy (0..55) into ring slot (yy%6): rows c = px+1 (1..56),
// cols = cin (fp16). Rows 0, 57..65 stay zero from the one-time zero fill.
// ---------------------------------------------------------------------------
__device__ __forceinline__ void stage_row(char* smem, const float* __restrict__ in, int yy){
    int ci = threadIdx.x >> 2, q = threadIdx.x & 3;
    uint32_t base = SM_RING + (uint32_t)(yy%6)*SLOT;
    const float* src = in + (size_t)ci*HW + yy*NW + q*14;
    uint32_t cb2 = (uint32_t)(ci*2);
    #pragma unroll 7
    for (int j=0;j<14;j++){
        int x = q*14 + j;
        float v = src[j];
        uint32_t c = (uint32_t)(x+1);
        uint32_t off = base + c*128 + (cb2 ^ ((c&7)<<4));
        *(__half*)(smem+off) = __float2half(v);
    }
}

// ---------------------------------------------------------------------------
// Persistent conv per (b,slot), HMMA fp16 2-term (W split hi/lo, X single).
// 8 warps = 2(wm) x 2(wn) x 2(rows), warp tile M32 x N32, 2 output rows/iter.
// MODE1: g_y1 = relu(bn1(conv(x)))
// MODE2: out += wt * relu(bn2(conv(g_y1)) + x)
// ---------------------------------------------------------------------------
template<int MODE>
__global__ void __launch_bounds__(256,1) conv_hmma(
    const float* __restrict__ x, const float* __restrict__ w_all,
    const float* __restrict__ bn_s, const float* __restrict__ bn_b,
    float* __restrict__ out)
{
    extern __shared__ char smem[];
    const int tid = threadIdx.x, wid = tid>>5, lane = tid&31;
    const int row = wid>>2;                  // output row within pair
    const int wm  = (wid>>1)&1;              // M tile wm*32
    const int wn  = (wid&1) ^ row;           // N tile wn*32 (xor balances SMSPs)
    const int bs = blockIdx.x, b = bs>>1;
    const int e = g_eidx[bs];
    const float wt = g_ewt[bs];
    const float* in   = (MODE==1) ? x + (size_t)b*CHW : g_y1 + (size_t)bs*CHW;
    const float* xres = x + (size_t)b*CHW;
    float* dst = (MODE==1) ? g_y1 + (size_t)bs*CHW : out + (size_t)b*CHW;
    const uint32_t sbase = smem_u32(smem);

    // zero ring once (halo row 0 and pad rows 57..65 stay zero forever)
    for (int i=tid; i<(6*SLOT)/4; i+=256) ((uint32_t*)(smem+SM_RING))[i] = 0;

    // stage weights once: tap g tile = [Wh rows co | +8192 Wl], swizzled fp16
    const float* wb = w_all + (size_t)e*NC*NC*9;
    for (int p=tid; p<4096; p+=256){
        int co = p>>6, ci = p&63;
        const float* wp = wb + (size_t)p*9;
        uint32_t sx = (uint32_t)((co&7)<<4);
        uint32_t ro = (uint32_t)co*128;
        uint32_t cb = (uint32_t)(ci*2);
        #pragma unroll
        for (int g9=0; g9<9; g9++){
            float v = wp[g9];
            __half h = __float2half(v);
            __half l = __float2half(v - __half2float(h));
            uint32_t off = SM_W + (uint32_t)g9*WTILE + ro + (cb ^ sx);
            *(__half*)(smem+off) = h;
            *(__half*)(smem+off+8192) = l;
        }
    }
    stage_row(smem, in, 0);
    stage_row(smem, in, 1);
    stage_row(smem, in, 2);

    // per-thread bn params
    const int g = lane>>2;
    float scv[2], biv[2], scv2[2], biv2[2];
    #pragma unroll
    for (int mt=0; mt<2; mt++){
        int co0 = wm*32 + mt*16 + g;
        scv[mt]  = bn_s[e*NC+co0];   biv[mt]  = bn_b[e*NC+co0];
        scv2[mt] = bn_s[e*NC+co0+8]; biv2[mt] = bn_b[e*NC+co0+8];
    }
    __syncthreads();

    // per-lane ldmatrix constants
    const int sub = lane>>3, r = lane&7;
    uint32_t rAoff[2], sxA[2];
    #pragma unroll
    for (int mt=0; mt<2; mt++){
        uint32_t rowA = (uint32_t)(wm*32 + mt*16 + (sub&1)*8 + r);
        rAoff[mt] = rowA*128;
        sxA[mt]   = (rowA&7)<<4;
    }
    const uint32_t kbA0 = (uint32_t)((sub>>1)*16);
    const uint32_t rb0  = (uint32_t)(wn*32 + (sub>>1)*8 + r);
    const uint32_t kbB0 = (uint32_t)((sub&1)*16);

    for (int y=0; y<NH; y+=2){
        // prefetch rows y+3, y+4 (slots disjoint from this iter's reads mod 6)
        if (y+3 < NH) stage_row(smem, in, y+3);
        if (y+4 < NH) stage_row(smem, in, y+4);

        const int yr = y + row;     // this warp's output row

        float C[2][4][4];
        #pragma unroll
        for (int mt=0;mt<2;mt++)
            #pragma unroll
            for (int j=0;j<4;j++)
                #pragma unroll
                for (int q=0;q<4;q++) C[mt][j][q]=0.f;

        for (int ky=0; ky<3; ky++){
            int iy = yr+ky-1;
            if (iy<0 || iy>=NH) continue;
            uint32_t slotB = sbase + SM_RING + (uint32_t)(iy%6)*SLOT;
            #pragma unroll
            for (int kx=0; kx<3; kx++){
                uint32_t aT = sbase + SM_W + (uint32_t)(3*ky+kx)*WTILE;
                #pragma unroll
                for (int ks=0; ks<4; ks++){
                    uint32_t kA = kbA0 + (uint32_t)ks*32;
                    uint32_t kB = kbB0 + (uint32_t)ks*32;
                    uint32_t ah[2][4], al[2][4], bf[2][4];
                    #pragma unroll
                    for (int mt=0; mt<2; mt++){
                        uint32_t a0 = aT + rAoff[mt] + (kA ^ sxA[mt]);
                        LDSM4(ah[mt][0],ah[mt][1],ah[mt][2],ah[mt][3], a0);
                        LDSM4(al[mt][0],al[mt][1],al[mt][2],al[mt][3], a0 + 8192);
                    }
                    #pragma unroll
                    for (int nt=0; nt<2; nt++){
                        uint32_t rb = rb0 + (uint32_t)(kx + nt*16);
                        uint32_t b0 = slotB + rb*128 + (kB ^ ((rb&7)<<4));
                        LDSM4(bf[nt][0],bf[nt][1],bf[nt][2],bf[nt][3], b0);
                    }
                    #pragma unroll
                    for (int mt=0;mt<2;mt++){
                        #pragma unroll
                        for (int nt=0;nt<2;nt++){
                            float* Cl = C[mt][nt*2];
                            MMA16816(Cl, ah[mt][0],ah[mt][1],ah[mt][2],ah[mt][3], bf[nt][0],bf[nt][1]);
                            MMA16816(Cl, al[mt][0],al[mt][1],al[mt][2],al[mt][3], bf[nt][0],bf[nt][1]);
                            if (!(wn==1 && nt==1)){   // px>=56 tile: all pad
                                float* Ch = C[mt][nt*2+1];
                                MMA16816(Ch, ah[mt][0],ah[mt][1],ah[mt][2],ah[mt][3], bf[nt][2],bf[nt][3]);
                                MMA16816(Ch, al[mt][0],al[mt][1],al[mt][2],al[mt][3], bf[nt][2],bf[nt][3]);
                            }
                        }
                    }
                }
            }
        }

        // epilogue: bn + (store | residual+relu+wt atomic add)
        int xq = 2*(lane&3);
        #pragma unroll
        for (int mt=0;mt<2;mt++){
            int co0 = wm*32 + mt*16 + g, co1 = co0+8;
            #pragma unroll
            for (int j=0;j<4;j++){
                int xx = wn*32 + j*8 + xq;
                if (xx >= NW) continue;
                float v0 = C[mt][j][0]*scv[mt]  + biv[mt];
                float v1 = C[mt][j][1]*scv[mt]  + biv[mt];
                float v2 = C[mt][j][2]*scv2[mt] + biv2[mt];
                float v3 = C[mt][j][3]*scv2[mt] + biv2[mt];
                int i0 = co0*HW + yr*NW + xx;
                int i1 = co1*HW + yr*NW + xx;
                if (MODE==1){
                    *(float2*)(dst+i0) = make_float2(fmaxf(v0,0.f), fmaxf(v1,0.f));
                    *(float2*)(dst+i1) = make_float2(fmaxf(v2,0.f), fmaxf(v3,0.f));
                } else {
                    float2 r0 = *(const float2*)(xres+i0);
                    float2 r1 = *(const float2*)(xres+i1);
                    atomicAdd(dst+i0,   wt*fmaxf(v0+r0.x,0.f));
                    atomicAdd(dst+i0+1, wt*fmaxf(v1+r0.y,0.f));
                    atomicAdd(dst+i1,   wt*fmaxf(v2+r1.x,0.f));
                    atomicAdd(dst+i1+1, wt*fmaxf(v3+r1.y,0.f));
                }
            }
        }
        __syncthreads();
    }
}

// ---------------------------------------------------------------------------
extern "C" void kernel_launch(void* const* d_in, const int* in_sizes, int n_in,
                              void* d_out, int out_size)
{
    const float* x       = (const float*)d_in[0];
    const float* gate_w  = (const float*)d_in[1];
    const float* gate_b  = (const float*)d_in[2];
    const float* conv1_w = (const float*)d_in[3];
    const float* bn1_s   = (const float*)d_in[4];
    const float* bn1_b   = (const float*)d_in[5];
    const float* conv2_w = (const float*)d_in[6];
    const float* bn2_s   = (const float*)d_in[7];
    const float* bn2_b   = (const float*)d_in[8];
    float* out = (float*)d_out;

    cudaMemsetAsync(d_out, 0, (size_t)out_size*sizeof(float), 0);
    pool_kernel<<<dim3(NB,8), 256>>>(x);
    float* dw = (out_size >= OUT_MAIN + NB*8) ? (out + OUT_MAIN) : nullptr;
    gate_fin<<<1, 64>>>(gate_w, gate_b, dw);

    cudaFuncSetAttribute(conv_hmma<1>, cudaFuncAttributeMaxDynamicSharedMemorySize, SM_TOTAL);
    cudaFuncSetAttribute(conv_hmma<2>, cudaFuncAttributeMaxDynamicSharedMemorySize, SM_TOTAL);
    conv_hmma<1><<<128, 256, SM_TOTAL>>>(x, conv1_w, bn1_s, bn1_b, nullptr);
    conv_hmma<2><<<128, 256, SM_TOTAL>>>(x, conv2_w, bn2_s, bn2_b, out);
}

// round 9
// speedup vs baseline: 2.6137x; 1.7975x over previous
#include <cuda_runtime.h>
#include <cuda_fp16.h>
#include <math.h>
#include <stdint.h>

#define NB 64
#define NC 64
#define NH 56
#define NW 56
#define HW 3136
#define CHW 200704
#define OUT_MAIN (NB*CHW)

__device__ int   g_eidx[NB*2];
__device__ float g_ewt[NB*2];
__device__ float g_pooled[NB*NC];

// ---- SMEM layout (bytes) ----
#define WT      8192                  // per tap: 64 rows x 128B fp16
#define SM_W1   0                     // 9 taps -> 73728
#define SM_W2   73728                 // 9 taps -> 147456
#define SLOT    8448                  // 66 rows x 128B
#define SM_XR   147456                // 6 slots -> 198144
#define SM_YR   198144                // 4 slots -> 231936
#define SM_TOTAL 231936               // <= 232448

__device__ __forceinline__ uint32_t smem_u32(const void* p){
    uint32_t a; asm("{ .reg .u64 t; cvta.to.shared.u64 t, %1; cvt.u32.u64 %0, t; }":"=r"(a):"l"(p)); return a;
}

#define LDSM4(d0,d1,d2,d3,a) \
    asm volatile("ldmatrix.sync.aligned.m8n8.x4.shared.b16 {%0,%1,%2,%3},[%4];" \
        : "=r"(d0),"=r"(d1),"=r"(d2),"=r"(d3) : "r"(a))

#define MMA16816(C,a0,a1,a2,a3,b0,b1) \
    asm volatile("mma.sync.aligned.m16n8k16.row.col.f32.f16.f16.f32 " \
        "{%0,%1,%2,%3},{%4,%5,%6,%7},{%8,%9},{%0,%1,%2,%3};" \
        : "+f"((C)[0]),"+f"((C)[1]),"+f"((C)[2]),"+f"((C)[3]) \
        : "r"(a0),"r"(a1),"r"(a2),"r"(a3),"r"(b0),"r"(b1))

// ---------------------------------------------------------------------------
// Gate: pooling (grid 64x8) + finalize (1x64)
// ---------------------------------------------------------------------------
__global__ void pool_kernel(const float* __restrict__ x){
    int b = blockIdx.x, gg = blockIdx.y;
    int w = threadIdx.x>>5, l = threadIdx.x&31;
    int c = gg*8 + w;
    const float4* p = (const float4*)(x + ((size_t)b*NC + c)*HW);
    float s = 0.f;
    for (int i=l; i<HW/4; i+=32){ float4 v = p[i]; s += (v.x+v.y)+(v.z+v.w); }
    #pragma unroll
    for (int o=16;o>0;o>>=1) s += __shfl_xor_sync(0xffffffffu, s, o);
    if (l==0) g_pooled[b*NC+c] = s * (1.0f/(float)HW);
}

__global__ void gate_fin(const float* __restrict__ gw, const float* __restrict__ gb,
                         float* __restrict__ dw){
    int b = threadIdx.x;
    if (b >= NB) return;
    float lg[8];
    #pragma unroll
    for (int e=0;e<8;e++){
        float s = gb[e];
        for (int c=0;c<NC;c++) s += g_pooled[b*NC+c]*gw[e*NC+c];
        lg[e] = s;
    }
    int i0=0; float v0=lg[0];
    #pragma unroll
    for (int e=1;e<8;e++) if (lg[e]>v0){ v0=lg[e]; i0=e; }
    int i1=-1; float v1=-1e30f;
    #pragma unroll
    for (int e=0;e<8;e++){ if (e==i0) continue; if (lg[e]>v1){ v1=lg[e]; i1=e; } }
    float w0 = 1.0f/(1.0f+expf(v1-v0));
    float w1 = 1.0f-w0;
    g_eidx[b*2+0]=i0; g_eidx[b*2+1]=i1;
    g_ewt [b*2+0]=w0; g_ewt [b*2+1]=w1;
    if (dw){ dw[b*8+i0]=w0; dw[b*8+i1]=w1; }
}

// ---------------------------------------------------------------------------
// Stage x row yy (0..55) into x-ring slot (yy%6): ring row c = px+1 (1..56),
// cols = cin (fp16 swizzled). Rows 0, 57..65 stay zero from one-time zero fill.
// ---------------------------------------------------------------------------
__device__ __forceinline__ void stage_x(char* smem, const float* __restrict__ in, int yy){
    int ci = threadIdx.x >> 2, q = threadIdx.x & 3;
    uint32_t base = SM_XR + (uint32_t)(yy%6)*SLOT;
    const float* src = in + (size_t)ci*HW + yy*NW + q*14;
    uint32_t cb2 = (uint32_t)(ci*2);
    #pragma unroll 7
    for (int j=0;j<14;j++){
        int x = q*14 + j;
        uint32_t c = (uint32_t)(x+1);
        uint32_t off = base + c*128 + (cb2 ^ ((c&7)<<4));
        *(__half*)(smem+off) = __float2half(src[j]);
    }
}

// ---------------------------------------------------------------------------
// One conv row (M64 x N64 x K taps*64), single-term fp16 HMMA, warp tile M32xN32.
// ---------------------------------------------------------------------------
template<int MOD>
__device__ __forceinline__ void conv_compute(
    uint32_t sbase, uint32_t wOff, uint32_t ringOff, int yr,
    const uint32_t* rAoff, const uint32_t* sxA, uint32_t kbA0,
    uint32_t rb0, uint32_t kbB0, int wn, float C[2][4][4])
{
    for (int ky=0; ky<3; ky++){
        int iy = yr+ky-1;
        if (iy<0 || iy>=NH) continue;
        uint32_t slotB = sbase + ringOff + (uint32_t)(iy%MOD)*SLOT;
        #pragma unroll
        for (int kx=0; kx<3; kx++){
            uint32_t aT = sbase + wOff + (uint32_t)(3*ky+kx)*WT;
            #pragma unroll
            for (int ks=0; ks<4; ks++){
                uint32_t kA = kbA0 + (uint32_t)ks*32;
                uint32_t kB = kbB0 + (uint32_t)ks*32;
                uint32_t a[2][4], bf[2][4];
                #pragma unroll
                for (int mt=0; mt<2; mt++){
                    uint32_t a0 = aT + rAoff[mt] + (kA ^ sxA[mt]);
                    LDSM4(a[mt][0],a[mt][1],a[mt][2],a[mt][3], a0);
                }
                #pragma unroll
                for (int nt=0; nt<2; nt++){
                    uint32_t rb = rb0 + (uint32_t)(kx + nt*16);
                    uint32_t b0 = slotB + rb*128 + (kB ^ ((rb&7)<<4));
                    LDSM4(bf[nt][0],bf[nt][1],bf[nt][2],bf[nt][3], b0);
                }
                #pragma unroll
                for (int mt=0;mt<2;mt++){
                    #pragma unroll
                    for (int nt=0;nt<2;nt++){
                        MMA16816(C[mt][nt*2], a[mt][0],a[mt][1],a[mt][2],a[mt][3], bf[nt][0],bf[nt][1]);
                        if (!(wn==1 && nt==1))
                            MMA16816(C[mt][nt*2+1], a[mt][0],a[mt][1],a[mt][2],a[mt][3], bf[nt][2],bf[nt][3]);
                    }
                }
            }
        }
    }
}

// ---------------------------------------------------------------------------
// Fused persistent BasicBlock per (b,slot): conv1 -> SMEM y1 ring (fp16, bn1+relu)
// -> conv2 one row-pair behind -> out += wt*relu(bn2(conv2)+x)
// 8 warps = 2(wm) x 2(wn) x 2(rows).
// ---------------------------------------------------------------------------
__global__ void __launch_bounds__(256,1) fused_block(
    const float* __restrict__ x,
    const float* __restrict__ w1_all, const float* __restrict__ bn1_s, const float* __restrict__ bn1_b,
    const float* __restrict__ w2_all, const float* __restrict__ bn2_s, const float* __restrict__ bn2_b,
    float* __restrict__ out)
{
    extern __shared__ char smem[];
    const int tid = threadIdx.x, wid = tid>>5, lane = tid&31;
    const int row = wid>>2;
    const int wm  = (wid>>1)&1;
    const int wn  = (wid&1) ^ row;
    const int bs = blockIdx.x, b = bs>>1;
    const int e = g_eidx[bs];
    const float wt = g_ewt[bs];
    const float* in = x + (size_t)b*CHW;
    float* dst = out + (size_t)b*CHW;
    const uint32_t sbase = smem_u32(smem);

    // zero both rings once (halo/pad rows stay zero forever)
    for (int i=tid; i<(SM_TOTAL-SM_XR)/4; i+=256) ((uint32_t*)(smem+SM_XR))[i] = 0;

    // stage both weight sets (single fp16, swizzled, tap-major tiles)
    for (int p=tid; p<4096; p+=256){
        int co = p>>6, ci = p&63;
        const float* wp1 = w1_all + (size_t)e*NC*NC*9 + (size_t)p*9;
        const float* wp2 = w2_all + (size_t)e*NC*NC*9 + (size_t)p*9;
        uint32_t off0 = (uint32_t)co*128 + (((uint32_t)(ci*2)) ^ ((uint32_t)(co&7)<<4));
        #pragma unroll
        for (int g9=0; g9<9; g9++){
            *(__half*)(smem + SM_W1 + g9*WT + off0) = __float2half(wp1[g9]);
            *(__half*)(smem + SM_W2 + g9*WT + off0) = __float2half(wp2[g9]);
        }
    }
    stage_x(smem, in, 0);
    stage_x(smem, in, 1);
    stage_x(smem, in, 2);

    // bn params for this warp's co lanes
    const int g = lane>>2;
    float s1a[2], b1a[2], s1b[2], b1b[2], s2a[2], b2a[2], s2b[2], b2b[2];
    #pragma unroll
    for (int mt=0; mt<2; mt++){
        int co0 = wm*32 + mt*16 + g;
        s1a[mt]=bn1_s[e*NC+co0];   b1a[mt]=bn1_b[e*NC+co0];
        s1b[mt]=bn1_s[e*NC+co0+8]; b1b[mt]=bn1_b[e*NC+co0+8];
        s2a[mt]=bn2_s[e*NC+co0];   b2a[mt]=bn2_b[e*NC+co0];
        s2b[mt]=bn2_s[e*NC+co0+8]; b2b[mt]=bn2_b[e*NC+co0+8];
    }
    __syncthreads();

    // per-lane ldmatrix constants
    const int sub = lane>>3, r = lane&7;
    uint32_t rAoff[2], sxA[2];
    #pragma unroll
    for (int mt=0; mt<2; mt++){
        uint32_t rowA = (uint32_t)(wm*32 + mt*16 + (sub&1)*8 + r);
        rAoff[mt] = rowA*128;
        sxA[mt]   = (rowA&7)<<4;
    }
    const uint32_t kbA0 = (uint32_t)((sub>>1)*16);
    const uint32_t rb0  = (uint32_t)(wn*32 + (sub>>1)*8 + r);
    const uint32_t kbB0 = (uint32_t)((sub&1)*16);
    const int xq = 2*(lane&3);

    for (int i=0; i<28; i++){
        int y2 = 2*i;
        if (y2+3 < NH) stage_x(smem, in, y2+3);
        if (y2+4 < NH) stage_x(smem, in, y2+4);

        // ---- conv1 pair (y2, y2+1) -> y1 ring ----
        {
            const int yr = y2 + row;
            float C[2][4][4];
            #pragma unroll
            for (int mt=0;mt<2;mt++)
                #pragma unroll
                for (int j=0;j<4;j++){ C[mt][j][0]=0;C[mt][j][1]=0;C[mt][j][2]=0;C[mt][j][3]=0; }
            conv_compute<6>(sbase, SM_W1, SM_XR, yr, rAoff, sxA, kbA0, rb0, kbB0, wn, C);

            char* yb = smem + SM_YR + (uint32_t)(yr&3)*SLOT;
            #pragma unroll
            for (int mt=0;mt<2;mt++){
                int co0 = wm*32 + mt*16 + g, co1 = co0+8;
                #pragma unroll
                for (int j=0;j<4;j++){
                    int xx = wn*32 + j*8 + xq;
                    if (xx >= NW) continue;
                    float v0 = fmaxf(C[mt][j][0]*s1a[mt] + b1a[mt], 0.f);
                    float v1 = fmaxf(C[mt][j][1]*s1a[mt] + b1a[mt], 0.f);
                    float v2 = fmaxf(C[mt][j][2]*s1b[mt] + b1b[mt], 0.f);
                    float v3 = fmaxf(C[mt][j][3]*s1b[mt] + b1b[mt], 0.f);
                    uint32_t c0 = (uint32_t)(xx+1), c1 = (uint32_t)(xx+2);
                    uint32_t sw0 = (c0&7)<<4, sw1 = (c1&7)<<4;
                    *(__half*)(yb + c0*128 + (((uint32_t)(co0*2)) ^ sw0)) = __float2half(v0);
                    *(__half*)(yb + c1*128 + (((uint32_t)(co0*2)) ^ sw1)) = __float2half(v1);
                    *(__half*)(yb + c0*128 + (((uint32_t)(co1*2)) ^ sw0)) = __float2half(v2);
                    *(__half*)(yb + c1*128 + (((uint32_t)(co1*2)) ^ sw1)) = __float2half(v3);
                }
            }
        }
        __syncthreads();   // y1 rows y2, y2+1 visible

        // ---- conv2 pair (y2-1, y2) -> out ----
        {
            const int yr = y2 - 1 + row;
            if (yr >= 0){
                float C[2][4][4];
                #pragma unroll
                for (int mt=0;mt<2;mt++)
                    #pragma unroll
                    for (int j=0;j<4;j++){ C[mt][j][0]=0;C[mt][j][1]=0;C[mt][j][2]=0;C[mt][j][3]=0; }
                conv_compute<4>(sbase, SM_W2, SM_YR, yr, rAoff, sxA, kbA0, rb0, kbB0, wn, C);

                #pragma unroll
                for (int mt=0;mt<2;mt++){
                    int co0 = wm*32 + mt*16 + g, co1 = co0+8;
                    #pragma unroll
                    for (int j=0;j<4;j++){
                        int xx = wn*32 + j*8 + xq;
                        if (xx >= NW) continue;
                        float v0 = C[mt][j][0]*s2a[mt] + b2a[mt];
                        float v1 = C[mt][j][1]*s2a[mt] + b2a[mt];
                        float v2 = C[mt][j][2]*s2b[mt] + b2b[mt];
                        float v3 = C[mt][j][3]*s2b[mt] + b2b[mt];
                        int i0 = co0*HW + yr*NW + xx;
                        int i1 = co1*HW + yr*NW + xx;
                        float2 r0 = *(const float2*)(in+i0);
                        float2 r1 = *(const float2*)(in+i1);
                        atomicAdd(dst+i0,   wt*fmaxf(v0+r0.x,0.f));
                        atomicAdd(dst+i0+1, wt*fmaxf(v1+r0.y,0.f));
                        atomicAdd(dst+i1,   wt*fmaxf(v2+r1.x,0.f));
                        atomicAdd(dst+i1+1, wt*fmaxf(v3+r1.y,0.f));
                    }
                }
            }
        }
        __syncthreads();   // protect y1/x ring slots before next iter's writes
    }

    // ---- tail: conv2 row 55 ----
    {
        const int yr = 55 + row;
        if (yr < NH){
            float C[2][4][4];
            #pragma unroll
            for (int mt=0;mt<2;mt++)
                #pragma unroll
                for (int j=0;j<4;j++){ C[mt][j][0]=0;C[mt][j][1]=0;C[mt][j][2]=0;C[mt][j][3]=0; }
            conv_compute<4>(sbase, SM_W2, SM_YR, yr, rAoff, sxA, kbA0, rb0, kbB0, wn, C);
            #pragma unroll
            for (int mt=0;mt<2;mt++){
                int co0 = wm*32 + mt*16 + g, co1 = co0+8;
                #pragma unroll
                for (int j=0;j<4;j++){
                    int xx = wn*32 + j*8 + xq;
                    if (xx >= NW) continue;
                    float v0 = C[mt][j][0]*s2a[mt] + b2a[mt];
                    float v1 = C[mt][j][1]*s2a[mt] + b2a[mt];
                    float v2 = C[mt][j][2]*s2b[mt] + b2b[mt];
                    float v3 = C[mt][j][3]*s2b[mt] + b2b[mt];
                    int i0 = co0*HW + yr*NW + xx;
                    int i1 = co1*HW + yr*NW + xx;
                    float2 r0 = *(const float2*)(in+i0);
                    float2 r1 = *(const float2*)(in+i1);
                    atomicAdd(dst+i0,   wt*fmaxf(v0+r0.x,0.f));
                    atomicAdd(dst+i0+1, wt*fmaxf(v1+r0.y,0.f));
                    atomicAdd(dst+i1,   wt*fmaxf(v2+r1.x,0.f));
                    atomicAdd(dst+i1+1, wt*fmaxf(v3+r1.y,0.f));
                }
            }
        }
    }
}

// ---------------------------------------------------------------------------
extern "C" void kernel_launch(void* const* d_in, const int* in_sizes, int n_in,
                              void* d_out, int out_size)
{
    const float* x       = (const float*)d_in[0];
    const float* gate_w  = (const float*)d_in[1];
    const float* gate_b  = (const float*)d_in[2];
    const float* conv1_w = (const float*)d_in[3];
    const float* bn1_s   = (const float*)d_in[4];
    const float* bn1_b   = (const float*)d_in[5];
    const float* conv2_w = (const float*)d_in[6];
    const float* bn2_s   = (const float*)d_in[7];
    const float* bn2_b   = (const float*)d_in[8];
    float* out = (float*)d_out;

    cudaMemsetAsync(d_out, 0, (size_t)out_size*sizeof(float), 0);
    pool_kernel<<<dim3(NB,8), 256>>>(x);
    float* dw = (out_size >= OUT_MAIN + NB*8) ? (out + OUT_MAIN) : nullptr;
    gate_fin<<<1, 64>>>(gate_w, gate_b, dw);

    cudaFuncSetAttribute(fused_block, cudaFuncAttributeMaxDynamicSharedMemorySize, SM_TOTAL);
    fused_block<<<128, 256, SM_TOTAL>>>(x, conv1_w, bn1_s, bn1_b,
                                        conv2_w, bn2_s, bn2_b, out);
}

// round 10
// speedup vs baseline: 2.6301x; 1.0063x over previous
#include <cuda_runtime.h>
#include <cuda_fp16.h>
#include <math.h>
#include <stdint.h>

#define NB 64
#define NC 64
#define NH 56
#define NW 56
#define HW 3136
#define CHW 200704
#define OUT_MAIN (NB*CHW)

__device__ int   g_eidx[NB*2];
__device__ float g_ewt[NB*2];
__device__ float g_pooled[NB*NC];

// ---- SMEM layout (bytes) ----
#define WT      8192                  // per tap: 64 rows x 128B fp16
#define SM_W1   0                     // 9 taps -> 73728
#define SM_W2   73728                 // 9 taps -> 147456
#define SLOT    8448                  // 66 rows x 128B
#define SM_XR   147456                // 6 slots -> 198144
#define SM_YR   198144                // 4 slots -> 231936
#define SM_TOTAL 231936               // <= 232448

__device__ __forceinline__ uint32_t smem_u32(const void* p){
    uint32_t a; asm("{ .reg .u64 t; cvta.to.shared.u64 t, %1; cvt.u32.u64 %0, t; }":"=r"(a):"l"(p)); return a;
}

#define LDSM4(d0,d1,d2,d3,a) \
    asm volatile("ldmatrix.sync.aligned.m8n8.x4.shared.b16 {%0,%1,%2,%3},[%4];" \
        : "=r"(d0),"=r"(d1),"=r"(d2),"=r"(d3) : "r"(a))

#define MMA16816(C,a0,a1,a2,a3,b0,b1) \
    asm volatile("mma.sync.aligned.m16n8k16.row.col.f32.f16.f16.f32 " \
        "{%0,%1,%2,%3},{%4,%5,%6,%7},{%8,%9},{%0,%1,%2,%3};" \
        : "+f"((C)[0]),"+f"((C)[1]),"+f"((C)[2]),"+f"((C)[3]) \
        : "r"(a0),"r"(a1),"r"(a2),"r"(a3),"r"(b0),"r"(b1))

// ---------------------------------------------------------------------------
// Gate: pooling (grid 64x8) + finalize (1x64)
// ---------------------------------------------------------------------------
__global__ void pool_kernel(const float* __restrict__ x){
    int b = blockIdx.x, gg = blockIdx.y;
    int w = threadIdx.x>>5, l = threadIdx.x&31;
    int c = gg*8 + w;
    const float4* p = (const float4*)(x + ((size_t)b*NC + c)*HW);
    float s = 0.f;
    for (int i=l; i<HW/4; i+=32){ float4 v = p[i]; s += (v.x+v.y)+(v.z+v.w); }
    #pragma unroll
    for (int o=16;o>0;o>>=1) s += __shfl_xor_sync(0xffffffffu, s, o);
    if (l==0) g_pooled[b*NC+c] = s * (1.0f/(float)HW);
}

__global__ void gate_fin(const float* __restrict__ gw, const float* __restrict__ gb,
                         float* __restrict__ dw){
    int b = threadIdx.x;
    if (b >= NB) return;
    float lg[8];
    #pragma unroll
    for (int e=0;e<8;e++){
        float s = gb[e];
        for (int c=0;c<NC;c++) s += g_pooled[b*NC+c]*gw[e*NC+c];
        lg[e] = s;
    }
    int i0=0; float v0=lg[0];
    #pragma unroll
    for (int e=1;e<8;e++) if (lg[e]>v0){ v0=lg[e]; i0=e; }
    int i1=-1; float v1=-1e30f;
    #pragma unroll
    for (int e=0;e<8;e++){ if (e==i0) continue; if (lg[e]>v1){ v1=lg[e]; i1=e; } }
    float w0 = 1.0f/(1.0f+expf(v1-v0));
    float w1 = 1.0f-w0;
    g_eidx[b*2+0]=i0; g_eidx[b*2+1]=i1;
    g_ewt [b*2+0]=w0; g_ewt [b*2+1]=w1;
    if (dw){ dw[b*8+i0]=w0; dw[b*8+i1]=w1; }
}

// ---------------------------------------------------------------------------
// Stage x row yy (0..55) into x-ring slot (yy%6): ring row c = px+1 (1..56),
// cols = cin (fp16 swizzled). Rows 0, 57..65 stay zero from one-time zero fill.
// ---------------------------------------------------------------------------
__device__ __forceinline__ void stage_x(char* smem, const float* __restrict__ in, int yy){
    int ci = threadIdx.x >> 2, q = threadIdx.x & 3;
    uint32_t base = SM_XR + (uint32_t)(yy%6)*SLOT;
    const float* src = in + (size_t)ci*HW + yy*NW + q*14;
    uint32_t cb2 = (uint32_t)(ci*2);
    #pragma unroll 7
    for (int j=0;j<14;j++){
        int x = q*14 + j;
        uint32_t c = (uint32_t)(x+1);
        uint32_t off = base + c*128 + (cb2 ^ ((c&7)<<4));
        *(__half*)(smem+off) = __float2half(src[j]);
    }
}

// ---------------------------------------------------------------------------
// One conv row (M64 x N64 x K taps*64), single-term fp16 HMMA, warp tile M32xN32.
// ---------------------------------------------------------------------------
template<int MOD>
__device__ __forceinline__ void conv_compute(
    uint32_t sbase, uint32_t wOff, uint32_t ringOff, int yr,
    const uint32_t* rAoff, const uint32_t* sxA, uint32_t kbA0,
    uint32_t rb0, uint32_t kbB0, int wn, float C[2][4][4])
{
    for (int ky=0; ky<3; ky++){
        int iy = yr+ky-1;
        if (iy<0 || iy>=NH) continue;
        uint32_t slotB = sbase + ringOff + (uint32_t)(iy%MOD)*SLOT;
        #pragma unroll
        for (int kx=0; kx<3; kx++){
            uint32_t aT = sbase + wOff + (uint32_t)(3*ky+kx)*WT;
            #pragma unroll
            for (int ks=0; ks<4; ks++){
                uint32_t kA = kbA0 + (uint32_t)ks*32;
                uint32_t kB = kbB0 + (uint32_t)ks*32;
                uint32_t a[2][4], bf[2][4];
                #pragma unroll
                for (int mt=0; mt<2; mt++){
                    uint32_t a0 = aT + rAoff[mt] + (kA ^ sxA[mt]);
                    LDSM4(a[mt][0],a[mt][1],a[mt][2],a[mt][3], a0);
                }
                #pragma unroll
                for (int nt=0; nt<2; nt++){
                    uint32_t rb = rb0 + (uint32_t)(kx + nt*16);
                    uint32_t b0 = slotB + rb*128 + (kB ^ ((rb&7)<<4));
                    LDSM4(bf[nt][0],bf[nt][1],bf[nt][2],bf[nt][3], b0);
                }
                #pragma unroll
                for (int mt=0;mt<2;mt++){
                    #pragma unroll
                    for (int nt=0;nt<2;nt++){
                        MMA16816(C[mt][nt*2], a[mt][0],a[mt][1],a[mt][2],a[mt][3], bf[nt][0],bf[nt][1]);
                        if (!(wn==1 && nt==1))
                            MMA16816(C[mt][nt*2+1], a[mt][0],a[mt][1],a[mt][2],a[mt][3], bf[nt][2],bf[nt][3]);
                    }
                }
            }
        }
    }
}

// ---------------------------------------------------------------------------
// Fused persistent BasicBlock per (b,slot): conv1 -> SMEM y1 ring (fp16, bn1+relu)
// -> conv2 one row-pair behind -> out += wt*relu(bn2(conv2)+x)
// 8 warps = 2(wm) x 2(wn) x 2(rows).
// ---------------------------------------------------------------------------
__global__ void __launch_bounds__(256,1) fused_block(
    const float* __restrict__ x,
    const float* __restrict__ w1_all, const float* __restrict__ bn1_s, const float* __restrict__ bn1_b,
    const float* __restrict__ w2_all, const float* __restrict__ bn2_s, const float* __restrict__ bn2_b,
    float* __restrict__ out)
{
    extern __shared__ char smem[];
    const int tid = threadIdx.x, wid = tid>>5, lane = tid&31;
    const int row = wid>>2;
    const int wm  = (wid>>1)&1;
    const int wn  = (wid&1) ^ row;
    const int bs = blockIdx.x, b = bs>>1;
    const int e = g_eidx[bs];
    const float wt = g_ewt[bs];
    const float* in = x + (size_t)b*CHW;
    float* dst = out + (size_t)b*CHW;
    const uint32_t sbase = smem_u32(smem);

    // zero both rings once (halo/pad rows stay zero forever)
    for (int i=tid; i<(SM_TOTAL-SM_XR)/4; i+=256) ((uint32_t*)(smem+SM_XR))[i] = 0;

    // stage both weight sets (single fp16, swizzled, tap-major tiles)
    for (int p=tid; p<4096; p+=256){
        int co = p>>6, ci = p&63;
        const float* wp1 = w1_all + (size_t)e*NC*NC*9 + (size_t)p*9;
        const float* wp2 = w2_all + (size_t)e*NC*NC*9 + (size_t)p*9;
        uint32_t off0 = (uint32_t)co*128 + (((uint32_t)(ci*2)) ^ ((uint32_t)(co&7)<<4));
        #pragma unroll
        for (int g9=0; g9<9; g9++){
            *(__half*)(smem + SM_W1 + g9*WT + off0) = __float2half(wp1[g9]);
            *(__half*)(smem + SM_W2 + g9*WT + off0) = __float2half(wp2[g9]);
        }
    }
    stage_x(smem, in, 0);
    stage_x(smem, in, 1);
    stage_x(smem, in, 2);

    // bn params for this warp's co lanes
    const int g = lane>>2;
    float s1a[2], b1a[2], s1b[2], b1b[2], s2a[2], b2a[2], s2b[2], b2b[2];
    #pragma unroll
    for (int mt=0; mt<2; mt++){
        int co0 = wm*32 + mt*16 + g;
        s1a[mt]=bn1_s[e*NC+co0];   b1a[mt]=bn1_b[e*NC+co0];
        s1b[mt]=bn1_s[e*NC+co0+8]; b1b[mt]=bn1_b[e*NC+co0+8];
        s2a[mt]=bn2_s[e*NC+co0];   b2a[mt]=bn2_b[e*NC+co0];
        s2b[mt]=bn2_s[e*NC+co0+8]; b2b[mt]=bn2_b[e*NC+co0+8];
    }
    __syncthreads();

    // per-lane ldmatrix constants
    const int sub = lane>>3, r = lane&7;
    uint32_t rAoff[2], sxA[2];
    #pragma unroll
    for (int mt=0; mt<2; mt++){
        uint32_t rowA = (uint32_t)(wm*32 + mt*16 + (sub&1)*8 + r);
        rAoff[mt] = rowA*128;
        sxA[mt]   = (rowA&7)<<4;
    }
    const uint32_t kbA0 = (uint32_t)((sub>>1)*16);
    const uint32_t rb0  = (uint32_t)(wn*32 + (sub>>1)*8 + r);
    const uint32_t kbB0 = (uint32_t)((sub&1)*16);
    const int xq = 2*(lane&3);

    for (int i=0; i<28; i++){
        int y2 = 2*i;
        if (y2+3 < NH) stage_x(smem, in, y2+3);
        if (y2+4 < NH) stage_x(smem, in, y2+4);

        // ---- conv1 pair (y2, y2+1) -> y1 ring ----
        {
            const int yr = y2 + row;
            float C[2][4][4];
            #pragma unroll
            for (int mt=0;mt<2;mt++)
                #pragma unroll
                for (int j=0;j<4;j++){ C[mt][j][0]=0;C[mt][j][1]=0;C[mt][j][2]=0;C[mt][j][3]=0; }
            conv_compute<6>(sbase, SM_W1, SM_XR, yr, rAoff, sxA, kbA0, rb0, kbB0, wn, C);

            char* yb = smem + SM_YR + (uint32_t)(yr&3)*SLOT;
            #pragma unroll
            for (int mt=0;mt<2;mt++){
                int co0 = wm*32 + mt*16 + g, co1 = co0+8;
                #pragma unroll
                for (int j=0;j<4;j++){
                    int xx = wn*32 + j*8 + xq;
                    if (xx >= NW) continue;
                    float v0 = fmaxf(C[mt][j][0]*s1a[mt] + b1a[mt], 0.f);
                    float v1 = fmaxf(C[mt][j][1]*s1a[mt] + b1a[mt], 0.f);
                    float v2 = fmaxf(C[mt][j][2]*s1b[mt] + b1b[mt], 0.f);
                    float v3 = fmaxf(C[mt][j][3]*s1b[mt] + b1b[mt], 0.f);
                    uint32_t c0 = (uint32_t)(xx+1), c1 = (uint32_t)(xx+2);
                    uint32_t sw0 = (c0&7)<<4, sw1 = (c1&7)<<4;
                    *(__half*)(yb + c0*128 + (((uint32_t)(co0*2)) ^ sw0)) = __float2half(v0);
                    *(__half*)(yb + c1*128 + (((uint32_t)(co0*2)) ^ sw1)) = __float2half(v1);
                    *(__half*)(yb + c0*128 + (((uint32_t)(co1*2)) ^ sw0)) = __float2half(v2);
                    *(__half*)(yb + c1*128 + (((uint32_t)(co1*2)) ^ sw1)) = __float2half(v3);
                }
            }
        }
        __syncthreads();   // y1 rows y2, y2+1 visible

        // ---- conv2 pair (y2-1, y2) -> out ----
        {
            const int yr = y2 - 1 + row;
            if (yr >= 0){
                float C[2][4][4];
                #pragma unroll
                for (int mt=0;mt<2;mt++)
                    #pragma unroll
                    for (int j=0;j<4;j++){ C[mt][j][0]=0;C[mt][j][1]=0;C[mt][j][2]=0;C[mt][j][3]=0; }
                conv_compute<4>(sbase, SM_W2, SM_YR, yr, rAoff, sxA, kbA0, rb0, kbB0, wn, C);

                #pragma unroll
                for (int mt=0;mt<2;mt++){
                    int co0 = wm*32 + mt*16 + g, co1 = co0+8;
                    #pragma unroll
                    for (int j=0;j<4;j++){
                        int xx = wn*32 + j*8 + xq;
                        if (xx >= NW) continue;
                        float v0 = C[mt][j][0]*s2a[mt] + b2a[mt];
                        float v1 = C[mt][j][1]*s2a[mt] + b2a[mt];
                        float v2 = C[mt][j][2]*s2b[mt] + b2b[mt];
                        float v3 = C[mt][j][3]*s2b[mt] + b2b[mt];
                        int i0 = co0*HW + yr*NW + xx;
                        int i1 = co1*HW + yr*NW + xx;
                        float2 r0 = *(const float2*)(in+i0);
                        float2 r1 = *(const float2*)(in+i1);
                        atomicAdd(dst+i0,   wt*fmaxf(v0+r0.x,0.f));
                        atomicAdd(dst+i0+1, wt*fmaxf(v1+r0.y,0.f));
                        atomicAdd(dst+i1,   wt*fmaxf(v2+r1.x,0.f));
                        atomicAdd(dst+i1+1, wt*fmaxf(v3+r1.y,0.f));
                    }
                }
            }
        }
        __syncthreads();   // protect y1/x ring slots before next iter's writes
    }

    // ---- tail: conv2 row 55 ----
    {
        const int yr = 55 + row;
        if (yr < NH){
            float C[2][4][4];
            #pragma unroll
            for (int mt=0;mt<2;mt++)
                #pragma unroll
                for (int j=0;j<4;j++){ C[mt][j][0]=0;C[mt][j][1]=0;C[mt][j][2]=0;C[mt][j][3]=0; }
            conv_compute<4>(sbase, SM_W2, SM_YR, yr, rAoff, sxA, kbA0, rb0, kbB0, wn, C);
            #pragma unroll
            for (int mt=0;mt<2;mt++){
                int co0 = wm*32 + mt*16 + g, co1 = co0+8;
                #pragma unroll
                for (int j=0;j<4;j++){
                    int xx = wn*32 + j*8 + xq;
                    if (xx >= NW) continue;
                    float v0 = C[mt][j][0]*s2a[mt] + b2a[mt];
                    float v1 = C[mt][j][1]*s2a[mt] + b2a[mt];
                    float v2 = C[mt][j][2]*s2b[mt] + b2b[mt];
                    float v3 = C[mt][j][3]*s2b[mt] + b2b[mt];
                    int i0 = co0*HW + yr*NW + xx;
                    int i1 = co1*HW + yr*NW + xx;
                    float2 r0 = *(const float2*)(in+i0);
                    float2 r1 = *(const float2*)(in+i1);
                    atomicAdd(dst+i0,   wt*fmaxf(v0+r0.x,0.f));
                    atomicAdd(dst+i0+1, wt*fmaxf(v1+r0.y,0.f));
                    atomicAdd(dst+i1,   wt*fmaxf(v2+r1.x,0.f));
                    atomicAdd(dst+i1+1, wt*fmaxf(v3+r1.y,0.f));
                }
            }
        }
    }
}

// ---------------------------------------------------------------------------
extern "C" void kernel_launch(void* const* d_in, const int* in_sizes, int n_in,
                              void* d_out, int out_size)
{
    const float* x       = (const float*)d_in[0];
    const float* gate_w  = (const float*)d_in[1];
    const float* gate_b  = (const float*)d_in[2];
    const float* conv1_w = (const float*)d_in[3];
    const float* bn1_s   = (const float*)d_in[4];
    const float* bn1_b   = (const float*)d_in[5];
    const float* conv2_w = (const float*)d_in[6];
    const float* bn2_s   = (const float*)d_in[7];
    const float* bn2_b   = (const float*)d_in[8];
    float* out = (float*)d_out;

    cudaMemsetAsync(d_out, 0, (size_t)out_size*sizeof(float), 0);
    pool_kernel<<<dim3(NB,8), 256>>>(x);
    float* dw = (out_size >= OUT_MAIN + NB*8) ? (out + OUT_MAIN) : nullptr;
    gate_fin<<<1, 64>>>(gate_w, gate_b, dw);

    cudaFuncSetAttribute(fused_block, cudaFuncAttributeMaxDynamicSharedMemorySize, SM_TOTAL);
    fused_block<<<128, 256, SM_TOTAL>>>(x, conv1_w, bn1_s, bn1_b,
                                        conv2_w, bn2_s, bn2_b, out);
}

// round 11
// speedup vs baseline: 2.8243x; 1.0738x over previous
#include <cuda_runtime.h>
#include <cuda_fp16.h>
#include <math.h>
#include <stdint.h>

#define NB 64
#define NC 64
#define NH 56
#define NW 56
#define HW 3136
#define CHW 200704
#define OUT_MAIN (NB*CHW)

__device__ int   g_eidx[NB*2];
__device__ float g_ewt[NB*2];
__device__ float g_pooled[NB*NC];

#define WT      8192
#define SM_W1   0
#define SM_W2   73728
#define SLOT    7424                 // 58 rows x 128B
#define SM_XR   147456               // 4 slots
#define SM_YR   177152               // 7 slots
#define SM_TOTAL 229120

__device__ __forceinline__ uint32_t smem_u32(const void* p){
    uint32_t a; asm("{ .reg .u64 t; cvta.to.shared.u64 t, %1; cvt.u32.u64 %0, t; }":"=r"(a):"l"(p)); return a;
}
#define LDSM4(d0,d1,d2,d3,a) \
    asm volatile("ldmatrix.sync.aligned.m8n8.x4.shared.b16 {%0,%1,%2,%3},[%4];" \
        : "=r"(d0),"=r"(d1),"=r"(d2),"=r"(d3) : "r"(a))
#define LDSM2(d0,d1,a) \
    asm volatile("ldmatrix.sync.aligned.m8n8.x2.shared.b16 {%0,%1},[%2];" \
        : "=r"(d0),"=r"(d1) : "r"(a))
#define MMA16816(C,a0,a1,a2,a3,b0,b1) \
    asm volatile("mma.sync.aligned.m16n8k16.row.col.f32.f16.f16.f32 " \
        "{%0,%1,%2,%3},{%4,%5,%6,%7},{%8,%9},{%0,%1,%2,%3};" \
        : "+f"((C)[0]),"+f"((C)[1]),"+f"((C)[2]),"+f"((C)[3]) \
        : "r"(a0),"r"(a1),"r"(a2),"r"(a3),"r"(b0),"r"(b1))

__global__ void pool_kernel(const float* __restrict__ x){
    int b = blockIdx.x, gg = blockIdx.y;
    int w = threadIdx.x>>5, l = threadIdx.x&31;
    int c = gg*8 + w;
    const float4* p = (const float4*)(x + ((size_t)b*NC + c)*HW);
    float s = 0.f;
    for (int i=l; i<HW/4; i+=32){ float4 v = p[i]; s += (v.x+v.y)+(v.z+v.w); }
    #pragma unroll
    for (int o=16;o>0;o>>=1) s += __shfl_xor_sync(0xffffffffu, s, o);
    if (l==0) g_pooled[b*NC+c] = s * (1.0f/(float)HW);
}

__global__ void gate_fin(const float* __restrict__ gw, const float* __restrict__ gb,
                         float* __restrict__ dw){
    int b = threadIdx.x;
    if (b >= NB) return;
    float lg[8];
    #pragma unroll
    for (int e=0;e<8;e++){
        float s = gb[e];
        for (int c=0;c<NC;c++) s += g_pooled[b*NC+c]*gw[e*NC+c];
        lg[e] = s;
    }
    int i0=0; float v0=lg[0];
    #pragma unroll
    for (int e=1;e<8;e++) if (lg[e]>v0){ v0=lg[e]; i0=e; }
    int i1=-1; float v1=-1e30f;
    #pragma unroll
    for (int e=0;e<8;e++){ if (e==i0) continue; if (lg[e]>v1){ v1=lg[e]; i1=e; } }
    float w0 = 1.0f/(1.0f+expf(v1-v0));
    g_eidx[b*2+0]=i0; g_eidx[b*2+1]=i1;
    g_ewt [b*2+0]=w0; g_ewt [b*2+1]=1.0f-w0;
    if (dw){ dw[b*8+i0]=w0; dw[b*8+i1]=1.0f-w0; }
}

__device__ __forceinline__ void loadx_regs(const float* __restrict__ in, int r,
                                           __half* hb, int tid){
    if (r >= NH) return;
    int ci = tid>>2, q = tid&3;
    const float* src = in + (size_t)ci*HW + r*NW + q*14;
    #pragma unroll
    for (int j=0;j<14;j++) hb[j] = __float2half(src[j]);
}
__device__ __forceinline__ void stsx_regs(char* smem, int r, const __half* hb, int tid){
    if (r >= NH) return;
    int ci = tid>>2, q = tid&3;
    uint32_t base = SM_XR + (uint32_t)(r&3)*SLOT;
    uint32_t cb2 = (uint32_t)(ci*2);
    #pragma unroll
    for (int j=0;j<14;j++){
        uint32_t c = (uint32_t)(q*14 + j + 1);
        *(__half*)(smem + base + c*128 + (cb2 ^ ((c&7)<<4))) = hb[j];
    }
}

// Warp computes M32xN32 for TWO adjacent rows; A frags shared, B rows shared.
template<int WN>
__device__ __forceinline__ void conv_pair(
    uint32_t sbase, uint32_t wOff, const uint32_t dyb[4], uint32_t vmask,
    const uint32_t rAoff[2], const uint32_t sxA[2], uint32_t kbA0,
    uint32_t rb0, uint32_t kbB0, uint32_t lane, float (&C)[2][2][4][4])
{
    #pragma unroll 1
    for (int kx=0; kx<3; kx++){
        #pragma unroll
        for (int ks=0; ks<4; ks++){
            uint32_t kA = kbA0 + (uint32_t)ks*32;
            uint32_t kB = kbB0 + (uint32_t)ks*32;
            uint32_t a[3][2][4];
            #pragma unroll
            for (int ky=0; ky<3; ky++){
                uint32_t aT = sbase + wOff + (uint32_t)(3*ky+kx)*WT;
                #pragma unroll
                for (int mt=0; mt<2; mt++)
                    LDSM4(a[ky][mt][0],a[ky][mt][1],a[ky][mt][2],a[ky][mt][3],
                          aT + rAoff[mt] + (kA ^ sxA[mt]));
            }
            #pragma unroll
            for (int d=0; d<4; d++){
                if (!((vmask>>d)&1u)) continue;
                uint32_t b[8];
                uint32_t rb = rb0 + (uint32_t)kx;
                LDSM4(b[0],b[1],b[2],b[3], dyb[d] + rb*128 + (kB ^ ((rb&7)<<4)));
                if (WN==0){
                    uint32_t rb2 = rb + 16;
                    LDSM4(b[4],b[5],b[6],b[7], dyb[d] + rb2*128 + (kB ^ ((rb2&7)<<4)));
                } else {
                    uint32_t rb2 = 48u + (lane&7) + (uint32_t)kx;
                    uint32_t kk = (uint32_t)ks*32 + ((lane>>3)&1u)*16u;
                    LDSM2(b[4],b[5], dyb[d] + rb2*128 + (kk ^ ((rb2&7)<<4)));
                }
                #pragma unroll
                for (int rr=0; rr<2; rr++){
                    int ky = d - rr;
                    if (ky < 0 || ky > 2) continue;
                    #pragma unroll
                    for (int mt=0; mt<2; mt++){
                        MMA16816(C[rr][mt][0], a[ky][mt][0],a[ky][mt][1],a[ky][mt][2],a[ky][mt][3], b[0],b[1]);
                        MMA16816(C[rr][mt][1], a[ky][mt][0],a[ky][mt][1],a[ky][mt][2],a[ky][mt][3], b[2],b[3]);
                        MMA16816(C[rr][mt][2], a[ky][mt][0],a[ky][mt][1],a[ky][mt][2],a[ky][mt][3], b[4],b[5]);
                        if (WN==0)
                        MMA16816(C[rr][mt][3], a[ky][mt][0],a[ky][mt][1],a[ky][mt][2],a[ky][mt][3], b[6],b[7]);
                    }
                }
            }
        }
    }
}

// Fused BasicBlock per (b,slot). 8 warps = 2cv x 2wm x 2wn.
// cv0: conv1 rows (y,y+1) -> y1 ring. cv1: conv2 rows (y-4,y-3) -> out.
__global__ void __launch_bounds__(256,1) fused_block(
    const float* __restrict__ x,
    const float* __restrict__ w1_all, const float* __restrict__ bn1_s, const float* __restrict__ bn1_b,
    const float* __restrict__ w2_all, const float* __restrict__ bn2_s, const float* __restrict__ bn2_b,
    float* __restrict__ out)
{
    extern __shared__ char smem[];
    const int tid = threadIdx.x, wid = tid>>5, lane = tid&31;
    const int cv = wid>>2;
    const int wm = (wid>>1)&1;
    const int wn = (wid&1)^cv;
    const int bs = blockIdx.x, b = bs>>1;
    const int e = g_eidx[bs];
    const float wt = g_ewt[bs];
    const float* in = x + (size_t)b*CHW;
    float* dst = out + (size_t)b*CHW;
    const uint32_t sbase = smem_u32(smem);

    for (int i=tid; i<(SM_TOTAL-SM_XR)/4; i+=256) ((uint32_t*)(smem+SM_XR))[i] = 0;

    for (int p=tid; p<4096; p+=256){
        int co = p>>6, ci = p&63;
        const float* wp1 = w1_all + (size_t)e*NC*NC*9 + (size_t)p*9;
        const float* wp2 = w2_all + (size_t)e*NC*NC*9 + (size_t)p*9;
        uint32_t off0 = (uint32_t)co*128 + (((uint32_t)(ci*2)) ^ ((uint32_t)(co&7)<<4));
        #pragma unroll
        for (int g9=0; g9<9; g9++){
            *(__half*)(smem + SM_W1 + g9*WT + off0) = __float2half(wp1[g9]);
            *(__half*)(smem + SM_W2 + g9*WT + off0) = __float2half(wp2[g9]);
        }
    }
    __syncthreads();          // zero-fill + weights complete before x staging
    {
        __half t[14];
        #pragma unroll
        for (int r=0;r<3;r++){ loadx_regs(in, r, t, tid); stsx_regs(smem, r, t, tid); }
    }

    const float* bsc = cv ? bn2_s : bn1_s;
    const float* bbi = cv ? bn2_b : bn1_b;
    const int g = lane>>2;
    float sa[2], ba[2], sb[2], bb[2];
    #pragma unroll
    for (int mt=0; mt<2; mt++){
        int co0 = wm*32 + mt*16 + g;
        sa[mt]=bsc[e*NC+co0];   ba[mt]=bbi[e*NC+co0];
        sb[mt]=bsc[e*NC+co0+8]; bb[mt]=bbi[e*NC+co0+8];
    }
    __syncthreads();

    const int sub = lane>>3, r = lane&7;
    uint32_t rAoff[2], sxA[2];
    #pragma unroll
    for (int mt=0; mt<2; mt++){
        uint32_t rowA = (uint32_t)(wm*32 + mt*16 + (sub&1)*8 + r);
        rAoff[mt] = rowA*128;
        sxA[mt]   = (rowA&7)<<4;
    }
    const uint32_t kbA0 = (uint32_t)((sub>>1)*16);
    const uint32_t rb0  = (uint32_t)(wn*32 + (sub>>1)*8 + r);
    const uint32_t kbB0 = (uint32_t)((sub&1)*16);
    const int xq = 2*(lane&3);
    const uint32_t wOff = cv ? SM_W2 : SM_W1;

    __half hb0[14], hb1[14];
    loadx_regs(in, 3, hb0, tid);
    loadx_regs(in, 4, hb1, tid);

    for (int it=0; it<30; it++){
        const int y = 2*it;
        if (it>0){
            stsx_regs(smem, y+1, hb0, tid);
            stsx_regs(smem, y+2, hb1, tid);
            __syncthreads();
            loadx_regs(in, y+3, hb0, tid);
            loadx_regs(in, y+4, hb1, tid);
        }
        const bool act = cv==0 ? (y < NH) : (y >= 4);
        if (act){
            const int r0 = cv==0 ? y : y-4;
            uint32_t dyb[4], vmask = 0;
            #pragma unroll
            for (int d=0; d<4; d++){
                int iy = r0 + d - 1;
                if (iy >= 0 && iy < NH) vmask |= 1u<<d;
                int ic = iy < 0 ? 0 : iy;
                dyb[d] = cv==0 ? sbase + SM_XR + (uint32_t)(ic&3)*SLOT
                               : sbase + SM_YR + (uint32_t)(ic%7)*SLOT;
            }
            float C[2][2][4][4];
            #pragma unroll
            for (int rr=0;rr<2;rr++)
                #pragma unroll
                for (int mt=0;mt<2;mt++)
                    #pragma unroll
                    for (int t=0;t<4;t++){ C[rr][mt][t][0]=0;C[rr][mt][t][1]=0;C[rr][mt][t][2]=0;C[rr][mt][t][3]=0; }

            if (wn==0) conv_pair<0>(sbase,wOff,dyb,vmask,rAoff,sxA,kbA0,rb0,kbB0,(uint32_t)lane,C);
            else       conv_pair<1>(sbase,wOff,dyb,vmask,rAoff,sxA,kbA0,rb0,kbB0,(uint32_t)lane,C);

            if (cv==0){
                #pragma unroll
                for (int rr=0;rr<2;rr++){
                    int yr = r0+rr;
                    char* yb = smem + SM_YR + (uint32_t)(yr%7)*SLOT;
                    #pragma unroll
                    for (int mt=0;mt<2;mt++){
                        int co0 = wm*32 + mt*16 + g, co1 = co0+8;
                        #pragma unroll
                        for (int t=0;t<4;t++){
                            if (wn==1 && t==3) continue;
                            int px = wn*32 + t*8 + xq;
                            float v0 = fmaxf(C[rr][mt][t][0]*sa[mt] + ba[mt], 0.f);
                            float v1 = fmaxf(C[rr][mt][t][1]*sa[mt] + ba[mt], 0.f);
                            float v2 = fmaxf(C[rr][mt][t][2]*sb[mt] + bb[mt], 0.f);
                            float v3 = fmaxf(C[rr][mt][t][3]*sb[mt] + bb[mt], 0.f);
                            uint32_t c0 = (uint32_t)(px+1), c1 = (uint32_t)(px+2);
                            uint32_t s0 = (c0&7)<<4, s1 = (c1&7)<<4;
                            *(__half*)(yb + c0*128 + (((uint32_t)(co0*2)) ^ s0)) = __float2half(v0);
                            *(__half*)(yb + c1*128 + (((uint32_t)(co0*2)) ^ s1)) = __float2half(v1);
                            *(__half*)(yb + c0*128 + (((uint32_t)(co1*2)) ^ s0)) = __float2half(v2);
                            *(__half*)(yb + c1*128 + (((uint32_t)(co1*2)) ^ s1)) = __float2half(v3);
                        }
                    }
                }
            } else {
                #pragma unroll
                for (int rr=0;rr<2;rr++){
                    int yr = r0+rr;
                    #pragma unroll
                    for (int mt=0;mt<2;mt++){
                        int co0 = wm*32 + mt*16 + g, co1 = co0+8;
                        #pragma unroll
                        for (int t=0;t<4;t++){
                            if (wn==1 && t==3) continue;
                            int px = wn*32 + t*8 + xq;
                            float v0 = C[rr][mt][t][0]*sa[mt] + ba[mt];
                            float v1 = C[rr][mt][t][1]*sa[mt] + ba[mt];
                            float v2 = C[rr][mt][t][2]*sb[mt] + bb[mt];
                            float v3 = C[rr][mt][t][3]*sb[mt] + bb[mt];
                            int i0 = co0*HW + yr*NW + px;
                            int i1 = co1*HW + yr*NW + px;
                            float2 r0v = *(const float2*)(in+i0);
                            float2 r1v = *(const float2*)(in+i1);
                            atomicAdd(dst+i0,   wt*fmaxf(v0+r0v.x,0.f));
                            atomicAdd(dst+i0+1, wt*fmaxf(v1+r0v.y,0.f));
                            atomicAdd(dst+i1,   wt*fmaxf(v2+r1v.x,0.f));
                            atomicAdd(dst+i1+1, wt*fmaxf(v3+r1v.y,0.f));
                        }
                    }
                }
            }
        }
        __syncthreads();
    }
}

extern "C" void kernel_launch(void* const* d_in, const int* in_sizes, int n_in,
                              void* d_out, int out_size)
{
    const float* x       = (const float*)d_in[0];
    const float* gate_w  = (const float*)d_in[1];
    const float* gate_b  = (const float*)d_in[2];
    const float* conv1_w = (const float*)d_in[3];
    const float* bn1_s   = (const float*)d_in[4];
    const float* bn1_b   = (const float*)d_in[5];
    const float* conv2_w = (const float*)d_in[6];
    const float* bn2_s   = (const float*)d_in[7];
    const float* bn2_b   = (const float*)d_in[8];
    float* out = (float*)d_out;

    cudaMemsetAsync(d_out, 0, (size_t)out_size*sizeof(float), 0);
    pool_kernel<<<dim3(NB,8), 256>>>(x);
    float* dw = (out_size >= OUT_MAIN + NB*8) ? (out + OUT_MAIN) : nullptr;
    gate_fin<<<1, 64>>>(gate_w, gate_b, dw);

    cudaFuncSetAttribute(fused_block, cudaFuncAttributeMaxDynamicSharedMemorySize, SM_TOTAL);
    fused_block<<<128, 256, SM_TOTAL>>>(x, conv1_w, bn1_s, bn1_b,
                                        conv2_w, bn2_s, bn2_b, out);
}

// round 12
// speedup vs baseline: 2.8413x; 1.0060x over previous
#include <cuda_runtime.h>
#include <cuda_fp16.h>
#include <math.h>
#include <stdint.h>

#define NB 64
#define NC 64
#define NH 56
#define NW 56
#define HW 3136
#define CHW 200704
#define OUT_MAIN (NB*CHW)

__device__ int   g_eidx[NB*2];
__device__ float g_ewt[NB*2];
__device__ float g_pooled[NB*NC];

#define WT      8192
#define SM_W1   0
#define SM_W2   73728
#define SLOT    7424                 // 58 rows x 128B
#define SM_XR   147456               // 4 slots
#define SM_YR   177152               // 7 slots
#define SM_TOTAL 229120

__device__ __forceinline__ uint32_t smem_u32(const void* p){
    uint32_t a; asm("{ .reg .u64 t; cvta.to.shared.u64 t, %1; cvt.u32.u64 %0, t; }":"=r"(a):"l"(p)); return a;
}
#define LDSM4(d0,d1,d2,d3,a) \
    asm volatile("ldmatrix.sync.aligned.m8n8.x4.shared.b16 {%0,%1,%2,%3},[%4];" \
        : "=r"(d0),"=r"(d1),"=r"(d2),"=r"(d3) : "r"(a))
#define LDSM2(d0,d1,a) \
    asm volatile("ldmatrix.sync.aligned.m8n8.x2.shared.b16 {%0,%1},[%2];" \
        : "=r"(d0),"=r"(d1) : "r"(a))
#define MMA16816(C,a0,a1,a2,a3,b0,b1) \
    asm volatile("mma.sync.aligned.m16n8k16.row.col.f32.f16.f16.f32 " \
        "{%0,%1,%2,%3},{%4,%5,%6,%7},{%8,%9},{%0,%1,%2,%3};" \
        : "+f"((C)[0]),"+f"((C)[1]),"+f"((C)[2]),"+f"((C)[3]) \
        : "r"(a0),"r"(a1),"r"(a2),"r"(a3),"r"(b0),"r"(b1))

// ---------------------------------------------------------------------------
// Pool + output zeroing fused (both DRAM-bound; saves one launch)
// ---------------------------------------------------------------------------
__global__ void pool_kernel(const float* __restrict__ x, float* __restrict__ zb, int zn4){
    int b = blockIdx.x, gg = blockIdx.y;
    int w = threadIdx.x>>5, l = threadIdx.x&31;
    int c = gg*8 + w;
    // zero slice of out (grid-stride float4)
    float4 z4 = make_float4(0.f,0.f,0.f,0.f);
    int gt = (blockIdx.y*gridDim.x + blockIdx.x)*blockDim.x + threadIdx.x;
    int nt = gridDim.x*gridDim.y*blockDim.x;
    for (int i=gt; i<zn4; i+=nt) ((float4*)zb)[i] = z4;

    const float4* p = (const float4*)(x + ((size_t)b*NC + c)*HW);
    float s = 0.f;
    for (int i=l; i<HW/4; i+=32){ float4 v = p[i]; s += (v.x+v.y)+(v.z+v.w); }
    #pragma unroll
    for (int o=16;o>0;o>>=1) s += __shfl_xor_sync(0xffffffffu, s, o);
    if (l==0) g_pooled[b*NC+c] = s * (1.0f/(float)HW);
}

__global__ void gate_fin(const float* __restrict__ gw, const float* __restrict__ gb,
                         float* __restrict__ dw){
    int b = threadIdx.x;
    if (b >= NB) return;
    float lg[8];
    #pragma unroll
    for (int e=0;e<8;e++){
        float s = gb[e];
        for (int c=0;c<NC;c++) s += g_pooled[b*NC+c]*gw[e*NC+c];
        lg[e] = s;
    }
    int i0=0; float v0=lg[0];
    #pragma unroll
    for (int e=1;e<8;e++) if (lg[e]>v0){ v0=lg[e]; i0=e; }
    int i1=-1; float v1=-1e30f;
    #pragma unroll
    for (int e=0;e<8;e++){ if (e==i0) continue; if (lg[e]>v1){ v1=lg[e]; i1=e; } }
    float w0 = 1.0f/(1.0f+expf(v1-v0));
    g_eidx[b*2+0]=i0; g_eidx[b*2+1]=i1;
    g_ewt [b*2+0]=w0; g_ewt [b*2+1]=1.0f-w0;
    if (dw){ dw[b*8+i0]=w0; dw[b*8+i1]=1.0f-w0; }
}

__device__ __forceinline__ void loadx_regs(const float* __restrict__ in, int r,
                                           __half* hb, int tid){
    if (r >= NH) return;
    int ci = tid>>2, q = tid&3;
    const float* src = in + (size_t)ci*HW + r*NW + q*14;
    #pragma unroll
    for (int j=0;j<14;j++) hb[j] = __float2half(src[j]);
}
__device__ __forceinline__ void stsx_regs(char* smem, int r, const __half* hb, int tid){
    if (r >= NH) return;
    int ci = tid>>2, q = tid&3;
    uint32_t base = SM_XR + (uint32_t)(r&3)*SLOT;
    uint32_t cb2 = (uint32_t)(ci*2);
    #pragma unroll
    for (int j=0;j<14;j++){
        uint32_t c = (uint32_t)(q*14 + j + 1);
        *(__half*)(smem + base + c*128 + (cb2 ^ ((c&7)<<4))) = hb[j];
    }
}

// Warp computes M32xN32 for TWO adjacent rows; A frags shared, B rows shared.
template<int WN>
__device__ __forceinline__ void conv_pair(
    uint32_t sbase, uint32_t wOff, const uint32_t dyb[4], uint32_t vmask,
    const uint32_t rAoff[2], const uint32_t sxA[2], uint32_t kbA0,
    uint32_t rb0, uint32_t kbB0, uint32_t lane, float (&C)[2][2][4][4])
{
    #pragma unroll 1
    for (int kx=0; kx<3; kx++){
        #pragma unroll
        for (int ks=0; ks<4; ks++){
            uint32_t kA = kbA0 + (uint32_t)ks*32;
            uint32_t kB = kbB0 + (uint32_t)ks*32;
            uint32_t a[3][2][4];
            #pragma unroll
            for (int ky=0; ky<3; ky++){
                uint32_t aT = sbase + wOff + (uint32_t)(3*ky+kx)*WT;
                #pragma unroll
                for (int mt=0; mt<2; mt++)
                    LDSM4(a[ky][mt][0],a[ky][mt][1],a[ky][mt][2],a[ky][mt][3],
                          aT + rAoff[mt] + (kA ^ sxA[mt]));
            }
            #pragma unroll
            for (int d=0; d<4; d++){
                if (!((vmask>>d)&1u)) continue;
                uint32_t b[8];
                uint32_t rb = rb0 + (uint32_t)kx;
                LDSM4(b[0],b[1],b[2],b[3], dyb[d] + rb*128 + (kB ^ ((rb&7)<<4)));
                if (WN==0){
                    uint32_t rb2 = rb + 16;
                    LDSM4(b[4],b[5],b[6],b[7], dyb[d] + rb2*128 + (kB ^ ((rb2&7)<<4)));
                } else {
                    uint32_t rb2 = 48u + (lane&7) + (uint32_t)kx;
                    uint32_t kk = (uint32_t)ks*32 + ((lane>>3)&1u)*16u;
                    LDSM2(b[4],b[5], dyb[d] + rb2*128 + (kk ^ ((rb2&7)<<4)));
                }
                #pragma unroll
                for (int rr=0; rr<2; rr++){
                    int ky = d - rr;
                    if (ky < 0 || ky > 2) continue;
                    #pragma unroll
                    for (int mt=0; mt<2; mt++){
                        MMA16816(C[rr][mt][0], a[ky][mt][0],a[ky][mt][1],a[ky][mt][2],a[ky][mt][3], b[0],b[1]);
                        MMA16816(C[rr][mt][1], a[ky][mt][0],a[ky][mt][1],a[ky][mt][2],a[ky][mt][3], b[2],b[3]);
                        MMA16816(C[rr][mt][2], a[ky][mt][0],a[ky][mt][1],a[ky][mt][2],a[ky][mt][3], b[4],b[5]);
                        if (WN==0)
                        MMA16816(C[rr][mt][3], a[ky][mt][0],a[ky][mt][1],a[ky][mt][2],a[ky][mt][3], b[6],b[7]);
                    }
                }
            }
        }
    }
}

// Fused BasicBlock per (b,slot). 8 warps = 2cv x 2wm x 2wn, 29 iters.
// it<28:  cv0 conv1 rows (y,y+1);  cv1 conv2 rows (y-4,y-3) for it>=2.
// it==28: BOTH run conv2 tail (cv0 rows 54-55, cv1 rows 52-53).
__global__ void __launch_bounds__(256,1) fused_block(
    const float* __restrict__ x,
    const float* __restrict__ w1_all, const float* __restrict__ bn1_s, const float* __restrict__ bn1_b,
    const float* __restrict__ w2_all, const float* __restrict__ bn2_s, const float* __restrict__ bn2_b,
    float* __restrict__ out)
{
    extern __shared__ char smem[];
    const int tid = threadIdx.x, wid = tid>>5, lane = tid&31;
    const int cv = wid>>2;
    const int wm = (wid>>1)&1;
    const int wn = (wid&1)^cv;
    const int bs = blockIdx.x, b = bs>>1;
    const int e = g_eidx[bs];
    const float wt = g_ewt[bs];
    const float* in = x + (size_t)b*CHW;
    float* dst = out + (size_t)b*CHW;
    const uint32_t sbase = smem_u32(smem);

    for (int i=tid; i<(SM_TOTAL-SM_XR)/4; i+=256) ((uint32_t*)(smem+SM_XR))[i] = 0;

    for (int p=tid; p<4096; p+=256){
        int co = p>>6, ci = p&63;
        const float* wp1 = w1_all + (size_t)e*NC*NC*9 + (size_t)p*9;
        const float* wp2 = w2_all + (size_t)e*NC*NC*9 + (size_t)p*9;
        uint32_t off0 = (uint32_t)co*128 + (((uint32_t)(ci*2)) ^ ((uint32_t)(co&7)<<4));
        #pragma unroll
        for (int g9=0; g9<9; g9++){
            *(__half*)(smem + SM_W1 + g9*WT + off0) = __float2half(wp1[g9]);
            *(__half*)(smem + SM_W2 + g9*WT + off0) = __float2half(wp2[g9]);
        }
    }
    __syncthreads();
    {
        __half t[14];
        #pragma unroll
        for (int r=0;r<3;r++){ loadx_regs(in, r, t, tid); stsx_regs(smem, r, t, tid); }
    }

    // both bn sets (needed for the iter-28 role swap)
    const int g = lane>>2;
    float s1a[2], b1a[2], s1b[2], b1b[2], s2a[2], b2a[2], s2b[2], b2b[2];
    #pragma unroll
    for (int mt=0; mt<2; mt++){
        int co0 = wm*32 + mt*16 + g;
        s1a[mt]=bn1_s[e*NC+co0];   b1a[mt]=bn1_b[e*NC+co0];
        s1b[mt]=bn1_s[e*NC+co0+8]; b1b[mt]=bn1_b[e*NC+co0+8];
        s2a[mt]=bn2_s[e*NC+co0];   b2a[mt]=bn2_b[e*NC+co0];
        s2b[mt]=bn2_s[e*NC+co0+8]; b2b[mt]=bn2_b[e*NC+co0+8];
    }
    __syncthreads();

    const int sub = lane>>3, r = lane&7;
    uint32_t rAoff[2], sxA[2];
    #pragma unroll
    for (int mt=0; mt<2; mt++){
        uint32_t rowA = (uint32_t)(wm*32 + mt*16 + (sub&1)*8 + r);
        rAoff[mt] = rowA*128;
        sxA[mt]   = (rowA&7)<<4;
    }
    const uint32_t kbA0 = (uint32_t)((sub>>1)*16);
    const uint32_t rb0  = (uint32_t)(wn*32 + (sub>>1)*8 + r);
    const uint32_t kbB0 = (uint32_t)((sub&1)*16);
    const int xq = 2*(lane&3);

    __half hb0[14], hb1[14];
    loadx_regs(in, 3, hb0, tid);
    loadx_regs(in, 4, hb1, tid);

    for (int it=0; it<29; it++){
        const int y = 2*it;
        if (it>0){
            stsx_regs(smem, y+1, hb0, tid);
            stsx_regs(smem, y+2, hb1, tid);
            __syncthreads();
            loadx_regs(in, y+3, hb0, tid);
            loadx_regs(in, y+4, hb1, tid);
        }
        const int role = (it==28) ? 1 : cv;               // 0=conv1, 1=conv2
        const bool act = (it==28) ? true : (cv==0 ? true : (it>=2));
        if (act){
            const int r0 = (it==28) ? (cv==0 ? 54 : 52) : (role==0 ? y : y-4);
            uint32_t dyb[4], vmask = 0;
            #pragma unroll
            for (int d=0; d<4; d++){
                int iy = r0 + d - 1;
                if (iy >= 0 && iy < NH) vmask |= 1u<<d;
                int ic = iy < 0 ? 0 : iy;
                dyb[d] = role==0 ? sbase + SM_XR + (uint32_t)(ic&3)*SLOT
                                 : sbase + SM_YR + (uint32_t)(ic%7)*SLOT;
            }
            float C[2][2][4][4];
            #pragma unroll
            for (int rr=0;rr<2;rr++)
                #pragma unroll
                for (int mt=0;mt<2;mt++)
                    #pragma unroll
                    for (int t=0;t<4;t++){ C[rr][mt][t][0]=0;C[rr][mt][t][1]=0;C[rr][mt][t][2]=0;C[rr][mt][t][3]=0; }

            const uint32_t wOff = role ? SM_W2 : SM_W1;
            if (wn==0) conv_pair<0>(sbase,wOff,dyb,vmask,rAoff,sxA,kbA0,rb0,kbB0,(uint32_t)lane,C);
            else       conv_pair<1>(sbase,wOff,dyb,vmask,rAoff,sxA,kbA0,rb0,kbB0,(uint32_t)lane,C);

            if (role==0){
                #pragma unroll
                for (int rr=0;rr<2;rr++){
                    int yr = r0+rr;
                    char* yb = smem + SM_YR + (uint32_t)(yr%7)*SLOT;
                    #pragma unroll
                    for (int mt=0;mt<2;mt++){
                        int co0 = wm*32 + mt*16 + g, co1 = co0+8;
                        #pragma unroll
                        for (int t=0;t<4;t++){
                            if (wn==1 && t==3) continue;
                            int px = wn*32 + t*8 + xq;
                            float v0 = fmaxf(C[rr][mt][t][0]*s1a[mt] + b1a[mt], 0.f);
                            float v1 = fmaxf(C[rr][mt][t][1]*s1a[mt] + b1a[mt], 0.f);
                            float v2 = fmaxf(C[rr][mt][t][2]*s1b[mt] + b1b[mt], 0.f);
                            float v3 = fmaxf(C[rr][mt][t][3]*s1b[mt] + b1b[mt], 0.f);
                            uint32_t c0 = (uint32_t)(px+1), c1 = (uint32_t)(px+2);
                            uint32_t s0 = (c0&7)<<4, s1 = (c1&7)<<4;
                            *(__half*)(yb + c0*128 + (((uint32_t)(co0*2)) ^ s0)) = __float2half(v0);
                            *(__half*)(yb + c1*128 + (((uint32_t)(co0*2)) ^ s1)) = __float2half(v1);
                            *(__half*)(yb + c0*128 + (((uint32_t)(co1*2)) ^ s0)) = __float2half(v2);
                            *(__half*)(yb + c1*128 + (((uint32_t)(co1*2)) ^ s1)) = __float2half(v3);
                        }
                    }
                }
            } else {
                #pragma unroll
                for (int rr=0;rr<2;rr++){
                    int yr = r0+rr;
                    #pragma unroll
                    for (int mt=0;mt<2;mt++){
                        int co0 = wm*32 + mt*16 + g, co1 = co0+8;
                        #pragma unroll
                        for (int t=0;t<4;t++){
                            if (wn==1 && t==3) continue;
                            int px = wn*32 + t*8 + xq;
                            float v0 = C[rr][mt][t][0]*s2a[mt] + b2a[mt];
                            float v1 = C[rr][mt][t][1]*s2a[mt] + b2a[mt];
                            float v2 = C[rr][mt][t][2]*s2b[mt] + b2b[mt];
                            float v3 = C[rr][mt][t][3]*s2b[mt] + b2b[mt];
                            int i0 = co0*HW + yr*NW + px;
                            int i1 = co1*HW + yr*NW + px;
                            float2 r0v = *(const float2*)(in+i0);
                            float2 r1v = *(const float2*)(in+i1);
                            atomicAdd(dst+i0,   wt*fmaxf(v0+r0v.x,0.f));
                            atomicAdd(dst+i0+1, wt*fmaxf(v1+r0v.y,0.f));
                            atomicAdd(dst+i1,   wt*fmaxf(v2+r1v.x,0.f));
                            atomicAdd(dst+i1+1, wt*fmaxf(v3+r1v.y,0.f));
                        }
                    }
                }
            }
        }
        __syncthreads();
    }
}

extern "C" void kernel_launch(void* const* d_in, const int* in_sizes, int n_in,
                              void* d_out, int out_size)
{
    const float* x       = (const float*)d_in[0];
    const float* gate_w  = (const float*)d_in[1];
    const float* gate_b  = (const float*)d_in[2];
    const float* conv1_w = (const float*)d_in[3];
    const float* bn1_s   = (const float*)d_in[4];
    const float* bn1_b   = (const float*)d_in[5];
    const float* conv2_w = (const float*)d_in[6];
    const float* bn2_s   = (const float*)d_in[7];
    const float* bn2_b   = (const float*)d_in[8];
    float* out = (float*)d_out;

    int n4 = out_size/4;
    if (out_size & 3) cudaMemsetAsync(d_out, 0, (size_t)out_size*sizeof(float), 0);
    pool_kernel<<<dim3(NB,8), 256>>>(x, (out_size&3) ? nullptr : out, (out_size&3) ? 0 : n4);
    float* dw = (out_size >= OUT_MAIN + NB*8) ? (out + OUT_MAIN) : nullptr;
    gate_fin<<<1, 64>>>(gate_w, gate_b, dw);

    cudaFuncSetAttribute(fused_block, cudaFuncAttributeMaxDynamicSharedMemorySize, SM_TOTAL);
    fused_block<<<128, 256, SM_TOTAL>>>(x, conv1_w, bn1_s, bn1_b,
                                        conv2_w, bn2_s, bn2_b, out);
}